// round 1
// baseline (speedup 1.0000x reference)
#include <cuda_runtime.h>

#define BATCH 256
#define HDIM  1024
#define EDIM  512
#define SDIM  128
#define VDIM  50257

// ---------------- scratch (no allocations allowed) ----------------
__device__ float g_Wh[BATCH * HDIM];
__device__ float g_score[SDIM * BATCH];
__device__ float g_ctx[BATCH * HDIM];
__device__ float g_g[BATCH * EDIM];
__device__ float g_gates[BATCH * 2 * HDIM];
__device__ float g_t1[BATCH * HDIM];
__device__ float g_t2[BATCH * HDIM];
__device__ float g_o1[BATCH * HDIM];

// ---------------- small helpers ----------------
__device__ __forceinline__ float warp_sum(float v) {
#pragma unroll
    for (int o = 16; o > 0; o >>= 1) v += __shfl_xor_sync(0xffffffffu, v, o);
    return v;
}
__device__ __forceinline__ float warp_max(float v) {
#pragma unroll
    for (int o = 16; o > 0; o >>= 1) v = fmaxf(v, __shfl_xor_sync(0xffffffffu, v, o));
    return v;
}

__global__ void zero_kernel(float* p, int n) {
    int i = blockIdx.x * blockDim.x + threadIdx.x;
    if (i < n) p[i] = 0.0f;
}

// ---------------- generic 128x128x8 SGEMM, 256 threads, 8x8 micro-tile ----------------
// P must provide: int K;  loadA4(row,k)->float4 ; loadB4(k,col)->float4 ;
//                 store(acc, m0, n0, tx, ty)
template <class P>
__launch_bounds__(256)
__global__ void gemm128(P p) {
    __shared__ float As[8][132];
    __shared__ float Bs[8][132];

    const int tid = threadIdx.x;
    const int tx = tid & 15, ty = tid >> 4;
    const int m0 = blockIdx.y * 128;
    const int n0 = blockIdx.x * 128;
    const int arow = tid >> 1, acol = (tid & 1) * 4;
    const int brow = tid >> 5, bcol = (tid & 31) * 4;

    float acc[8][8];
#pragma unroll
    for (int i = 0; i < 8; i++)
#pragma unroll
        for (int j = 0; j < 8; j++) acc[i][j] = 0.0f;

    for (int k0 = 0; k0 < p.K; k0 += 8) {
        float4 av = p.loadA4(m0 + arow, k0 + acol);
        As[acol + 0][arow] = av.x;
        As[acol + 1][arow] = av.y;
        As[acol + 2][arow] = av.z;
        As[acol + 3][arow] = av.w;
        float4 bv = p.loadB4(k0 + brow, n0 + bcol);
        *(float4*)&Bs[brow][bcol] = bv;
        __syncthreads();
#pragma unroll
        for (int kk = 0; kk < 8; kk++) {
            float a[8], b[8];
#pragma unroll
            for (int i = 0; i < 8; i++) a[i] = As[kk][ty * 8 + i];
#pragma unroll
            for (int j = 0; j < 8; j++) b[j] = Bs[kk][tx * 8 + j];
#pragma unroll
            for (int i = 0; i < 8; i++)
#pragma unroll
                for (int j = 0; j < 8; j++) acc[i][j] = fmaf(a[i], b[j], acc[i][j]);
        }
        __syncthreads();
    }
    p.store(acc, m0, n0, tx, ty);
}

// ---------------- GEMM problem functors ----------------
// act: 0=none, 1=relu, 2=sigmoid
struct ProbPlain {
    const float* A;
    const float* B;
    const float* bias;
    float* C;
    int K;
    int N;
    int act;
    __device__ __forceinline__ float4 loadA4(int r, int k) const {
        return *(const float4*)(A + (size_t)r * K + k);
    }
    __device__ __forceinline__ float4 loadB4(int k, int c) const {
        return *(const float4*)(B + (size_t)k * N + c);
    }
    __device__ __forceinline__ void store(const float (&acc)[8][8], int m0, int n0,
                                          int tx, int ty) const {
#pragma unroll
        for (int i = 0; i < 8; i++) {
            int r = m0 + ty * 8 + i;
#pragma unroll
            for (int j = 0; j < 8; j++) {
                int c = n0 + tx * 8 + j;
                float v = acc[i][j] + bias[c];
                if (act == 1) v = fmaxf(v, 0.0f);
                else if (act == 2) v = 1.0f / (1.0f + expf(-v));
                C[(size_t)r * N + c] = v;
            }
        }
    }
};

// g = relu( [emb[ids], ctx] @ comb_w + comb_b ),  K = E + H = 1536, N = E = 512
struct ProbComb {
    const float* emb;
    const int* ids;
    const float* ctx;
    const float* B;
    const float* bias;
    float* C;
    int K;
    int N;
    __device__ __forceinline__ float4 loadA4(int r, int k) const {
        if (k < EDIM)
            return *(const float4*)(emb + (size_t)__ldg(&ids[r]) * EDIM + k);
        return *(const float4*)(ctx + (size_t)r * HDIM + (k - EDIM));
    }
    __device__ __forceinline__ float4 loadB4(int k, int c) const {
        return *(const float4*)(B + (size_t)k * N + c);
    }
    __device__ __forceinline__ void store(const float (&acc)[8][8], int m0, int n0,
                                          int tx, int ty) const {
#pragma unroll
        for (int i = 0; i < 8; i++) {
            int r = m0 + ty * 8 + i;
#pragma unroll
            for (int j = 0; j < 8; j++) {
                int c = n0 + tx * 8 + j;
                float v = fmaxf(acc[i][j] + bias[c], 0.0f);
                C[(size_t)r * N + c] = v;
            }
        }
    }
};

// gates = sigmoid( [g, hidden] @ [ih_w; hh_w] + ih_b + hh_b ),  K=1536, N=2048
struct ProbGates {
    const float* gA;
    const float* hid;
    const float* ihw;
    const float* hhw;
    const float* ihb;
    const float* hhb;
    float* C;
    int K;
    int N;
    __device__ __forceinline__ float4 loadA4(int r, int k) const {
        if (k < EDIM) return *(const float4*)(gA + (size_t)r * EDIM + k);
        return *(const float4*)(hid + (size_t)r * HDIM + (k - EDIM));
    }
    __device__ __forceinline__ float4 loadB4(int k, int c) const {
        if (k < EDIM) return *(const float4*)(ihw + (size_t)k * N + c);
        return *(const float4*)(hhw + (size_t)(k - EDIM) * N + c);
    }
    __device__ __forceinline__ void store(const float (&acc)[8][8], int m0, int n0,
                                          int tx, int ty) const {
#pragma unroll
        for (int i = 0; i < 8; i++) {
            int r = m0 + ty * 8 + i;
#pragma unroll
            for (int j = 0; j < 8; j++) {
                int c = n0 + tx * 8 + j;
                float v = acc[i][j] + ihb[c] + hhb[c];
                v = 1.0f / (1.0f + expf(-v));
                C[(size_t)r * N + c] = v;
            }
        }
    }
};

// logits = o1 @ out2_w + out2_b ; N = 50257 (not /4) -> guarded scalar B loads
struct ProbOut2 {
    const float* A;
    const float* B;
    const float* bias;
    float* C;
    int K;
    int N;
    __device__ __forceinline__ float4 loadA4(int r, int k) const {
        return *(const float4*)(A + (size_t)r * K + k);
    }
    __device__ __forceinline__ float4 loadB4(int k, int c) const {
        const float* p = B + (size_t)k * N;
        float4 v;
        v.x = (c + 0 < N) ? __ldg(p + c + 0) : 0.0f;
        v.y = (c + 1 < N) ? __ldg(p + c + 1) : 0.0f;
        v.z = (c + 2 < N) ? __ldg(p + c + 2) : 0.0f;
        v.w = (c + 3 < N) ? __ldg(p + c + 3) : 0.0f;
        return v;
    }
    __device__ __forceinline__ void store(const float (&acc)[8][8], int m0, int n0,
                                          int tx, int ty) const {
#pragma unroll
        for (int i = 0; i < 8; i++) {
            int r = m0 + ty * 8 + i;
#pragma unroll
            for (int j = 0; j < 8; j++) {
                int c = n0 + tx * 8 + j;
                if (c < N) C[(size_t)r * N + c] = acc[i][j] + bias[c];
            }
        }
    }
};

// ---------------- fused attention-score GEMM ----------------
// score[m] += sum_c tanh( enc@U_w [m,c] + Wh[m%BATCH, c] + U_b[c] ) * v_w[c]
__launch_bounds__(256)
__global__ void score_gemm_kernel(const float* __restrict__ enc,
                                  const float* __restrict__ Uw,
                                  const float* __restrict__ Ub,
                                  const float* __restrict__ Wh,
                                  const float* __restrict__ vw,
                                  float* __restrict__ score) {
    __shared__ float As[8][132];
    __shared__ float Bs[8][132];
    __shared__ float red[16][128];

    const int tid = threadIdx.x;
    const int tx = tid & 15, ty = tid >> 4;
    const int m0 = blockIdx.y * 128;
    const int n0 = blockIdx.x * 128;
    const int arow = tid >> 1, acol = (tid & 1) * 4;
    const int brow = tid >> 5, bcol = (tid & 31) * 4;

    float acc[8][8];
#pragma unroll
    for (int i = 0; i < 8; i++)
#pragma unroll
        for (int j = 0; j < 8; j++) acc[i][j] = 0.0f;

    for (int k0 = 0; k0 < HDIM; k0 += 8) {
        float4 av = *(const float4*)(enc + (size_t)(m0 + arow) * HDIM + k0 + acol);
        As[acol + 0][arow] = av.x;
        As[acol + 1][arow] = av.y;
        As[acol + 2][arow] = av.z;
        As[acol + 3][arow] = av.w;
        *(float4*)&Bs[brow][bcol] =
            *(const float4*)(Uw + (size_t)(k0 + brow) * HDIM + n0 + bcol);
        __syncthreads();
#pragma unroll
        for (int kk = 0; kk < 8; kk++) {
            float a[8], b[8];
#pragma unroll
            for (int i = 0; i < 8; i++) a[i] = As[kk][ty * 8 + i];
#pragma unroll
            for (int j = 0; j < 8; j++) b[j] = Bs[kk][tx * 8 + j];
#pragma unroll
            for (int i = 0; i < 8; i++)
#pragma unroll
                for (int j = 0; j < 8; j++) acc[i][j] = fmaf(a[i], b[j], acc[i][j]);
        }
        __syncthreads();
    }

    // epilogue: tanh + dot with v_w, reduce per row
#pragma unroll
    for (int i = 0; i < 8; i++) {
        int m = m0 + ty * 8 + i;
        int nn = m & (BATCH - 1);
        const float* whr = Wh + (size_t)nn * HDIM;
        float s = 0.0f;
#pragma unroll
        for (int j = 0; j < 8; j++) {
            int c = n0 + tx * 8 + j;
            float t = tanhf(acc[i][j] + whr[c] + Ub[c]);
            s = fmaf(t, vw[c], s);
        }
        red[tx][ty * 8 + i] = s;
    }
    __syncthreads();
    if (tid < 128) {
        float s = 0.0f;
#pragma unroll
        for (int q = 0; q < 16; q++) s += red[q][tid];
        atomicAdd(&score[m0 + tid], s);
    }
}

// ---------------- softmax over S (axis 0) -> attn output ----------------
__global__ void softmax_kernel(const float* __restrict__ score,
                               float* __restrict__ attn_out) {
    const int n = blockIdx.x;
    const int s = threadIdx.x;  // 128 threads
    float v = score[s * BATCH + n];

    __shared__ float rmax[4], rsum[4];
    float m = warp_max(v);
    if ((s & 31) == 0) rmax[s >> 5] = m;
    __syncthreads();
    m = fmaxf(fmaxf(rmax[0], rmax[1]), fmaxf(rmax[2], rmax[3]));

    float e = expf(v - m);
    float t = warp_sum(e);
    if ((s & 31) == 0) rsum[s >> 5] = t;
    __syncthreads();
    float sum = rsum[0] + rsum[1] + rsum[2] + rsum[3];

    attn_out[s * BATCH + n] = e / sum;
}

// ---------------- context[n,:] = sum_s attn[s,n] * enc[s,n,:] ----------------
__global__ void context_kernel(const float* __restrict__ enc,
                               const float* __restrict__ attn,
                               float* __restrict__ ctx) {
    const int n = blockIdx.x;
    const int tid = threadIdx.x;  // 256 threads, float4 each
    __shared__ float a[SDIM];
    if (tid < SDIM) a[tid] = attn[tid * BATCH + n];
    __syncthreads();
    float4 acc = make_float4(0.f, 0.f, 0.f, 0.f);
    for (int s = 0; s < SDIM; s++) {
        float4 e = ((const float4*)(enc + ((size_t)s * BATCH + n) * HDIM))[tid];
        float w = a[s];
        acc.x = fmaf(w, e.x, acc.x);
        acc.y = fmaf(w, e.y, acc.y);
        acc.z = fmaf(w, e.z, acc.z);
        acc.w = fmaf(w, e.w, acc.w);
    }
    ((float4*)(ctx + (size_t)n * HDIM))[tid] = acc;
}

// ---------------- GRU combine + LayerNorm -> h output ----------------
__global__ void fuse_hln_kernel(const float* __restrict__ gates,
                                const float* __restrict__ t1,
                                const float* __restrict__ t2,
                                const float* __restrict__ hid,
                                const float* __restrict__ lng,
                                const float* __restrict__ lnb,
                                float* __restrict__ hout) {
    const int n = blockIdx.x;
    const int tid = threadIdx.x;  // 256 threads, float4 each
    float4 z = ((const float4*)(gates + (size_t)n * 2 * HDIM))[tid];
    float4 r = ((const float4*)(gates + (size_t)n * 2 * HDIM + HDIM))[tid];
    float4 a = ((const float4*)(t1 + (size_t)n * HDIM))[tid];
    float4 b = ((const float4*)(t2 + (size_t)n * HDIM))[tid];
    float4 hv = ((const float4*)(hid + (size_t)n * HDIM))[tid];

    float4 hr;
    hr.x = (1.0f - z.x) * hv.x + z.x * tanhf(a.x + r.x * b.x);
    hr.y = (1.0f - z.y) * hv.y + z.y * tanhf(a.y + r.y * b.y);
    hr.z = (1.0f - z.z) * hv.z + z.z * tanhf(a.z + r.z * b.z);
    hr.w = (1.0f - z.w) * hv.w + z.w * tanhf(a.w + r.w * b.w);

    float s = hr.x + hr.y + hr.z + hr.w;
    float ss = hr.x * hr.x + hr.y * hr.y + hr.z * hr.z + hr.w * hr.w;

    __shared__ float sm1[8], sm2[8];
    float w1 = warp_sum(s), w2 = warp_sum(ss);
    if ((tid & 31) == 0) { sm1[tid >> 5] = w1; sm2[tid >> 5] = w2; }
    __syncthreads();
    float tot1 = 0.f, tot2 = 0.f;
#pragma unroll
    for (int q = 0; q < 8; q++) { tot1 += sm1[q]; tot2 += sm2[q]; }

    float mu = tot1 * (1.0f / HDIM);
    float var = tot2 * (1.0f / HDIM) - mu * mu;
    float inv = rsqrtf(var + 1e-5f);

    float4 gg = ((const float4*)lng)[tid];
    float4 bb = ((const float4*)lnb)[tid];
    float4 o;
    o.x = (hr.x - mu) * inv * gg.x + bb.x;
    o.y = (hr.y - mu) * inv * gg.y + bb.y;
    o.z = (hr.z - mu) * inv * gg.z + bb.z;
    o.w = (hr.w - mu) * inv * gg.w + bb.w;
    ((float4*)(hout + (size_t)n * HDIM))[tid] = o;
}

// ---------------- log_softmax in place, one block per row ----------------
__global__ void logsoftmax_kernel(float* __restrict__ logits) {
    const int n = blockIdx.x;
    const int tid = threadIdx.x;  // 512 threads
    float* row = logits + (size_t)n * VDIM;
    __shared__ float sm[16];

    float m = -3.4e38f;
    for (int i = tid; i < VDIM; i += 512) m = fmaxf(m, row[i]);
    m = warp_max(m);
    if ((tid & 31) == 0) sm[tid >> 5] = m;
    __syncthreads();
    float mx = -3.4e38f;
#pragma unroll
    for (int q = 0; q < 16; q++) mx = fmaxf(mx, sm[q]);
    __syncthreads();

    float s = 0.0f;
    for (int i = tid; i < VDIM; i += 512) s += expf(row[i] - mx);
    s = warp_sum(s);
    if ((tid & 31) == 0) sm[tid >> 5] = s;
    __syncthreads();
    float tot = 0.0f;
#pragma unroll
    for (int q = 0; q < 16; q++) tot += sm[q];
    float lse = mx + logf(tot);

    for (int i = tid; i < VDIM; i += 512) row[i] = row[i] - lse;
}

// ---------------- launch ----------------
extern "C" void kernel_launch(void* const* d_in, const int* in_sizes, int n_in,
                              void* d_out, int out_size) {
    const int* ids = (const int*)d_in[0];
    const float* hidden = (const float*)d_in[1];
    const float* enc = (const float*)d_in[2];
    const float* emb = (const float*)d_in[3];
    const float* W_w = (const float*)d_in[4];
    const float* W_b = (const float*)d_in[5];
    const float* U_w = (const float*)d_in[6];
    const float* U_b = (const float*)d_in[7];
    const float* v_w = (const float*)d_in[8];
    // d_in[9] = v_b : constant shift over S, cancels in softmax; score itself is not an output
    const float* ih_w = (const float*)d_in[10];
    const float* ih_b = (const float*)d_in[11];
    const float* hh_w = (const float*)d_in[12];
    const float* hh_b = (const float*)d_in[13];
    const float* cand_w = (const float*)d_in[14];
    const float* cand_b = (const float*)d_in[15];
    const float* hhc_w = (const float*)d_in[16];
    const float* hhc_b = (const float*)d_in[17];
    const float* comb_w = (const float*)d_in[18];
    const float* comb_b = (const float*)d_in[19];
    const float* ln_g = (const float*)d_in[20];
    const float* ln_b = (const float*)d_in[21];
    const float* out1_w = (const float*)d_in[22];
    const float* out1_b = (const float*)d_in[23];
    const float* out2_w = (const float*)d_in[24];
    const float* out2_b = (const float*)d_in[25];

    float* out_logits = (float*)d_out;
    float* out_h = out_logits + (size_t)BATCH * VDIM;
    float* out_attn = out_h + (size_t)BATCH * HDIM;

    float *Wh, *score, *ctx, *gbuf, *gates, *t1, *t2, *o1;
    cudaGetSymbolAddress((void**)&Wh, g_Wh);
    cudaGetSymbolAddress((void**)&score, g_score);
    cudaGetSymbolAddress((void**)&ctx, g_ctx);
    cudaGetSymbolAddress((void**)&gbuf, g_g);
    cudaGetSymbolAddress((void**)&gates, g_gates);
    cudaGetSymbolAddress((void**)&t1, g_t1);
    cudaGetSymbolAddress((void**)&t2, g_t2);
    cudaGetSymbolAddress((void**)&o1, g_o1);

    // 1. Wh = hidden @ W_w + W_b
    {
        ProbPlain p{hidden, W_w, W_b, Wh, HDIM, HDIM, 0};
        gemm128<ProbPlain><<<dim3(HDIM / 128, BATCH / 128), 256>>>(p);
    }
    // 2. zero score accumulator
    zero_kernel<<<(SDIM * BATCH + 255) / 256, 256>>>(score, SDIM * BATCH);
    // 3. fused score GEMM (enc @ U_w -> tanh -> dot v_w)
    score_gemm_kernel<<<dim3(HDIM / 128, (SDIM * BATCH) / 128), 256>>>(
        enc, U_w, U_b, Wh, v_w, score);
    // 4. softmax over S -> attn output section
    softmax_kernel<<<BATCH, SDIM>>>(score, out_attn);
    // 5. context
    context_kernel<<<BATCH, 256>>>(enc, out_attn, ctx);
    // 6. g = relu([emb[ids], ctx] @ comb_w + comb_b)
    {
        ProbComb p{emb, ids, ctx, comb_w, comb_b, gbuf, EDIM + HDIM, EDIM};
        gemm128<ProbComb><<<dim3(EDIM / 128, BATCH / 128), 256>>>(p);
    }
    // 7. gates = sigmoid([g, hidden] @ [ih_w; hh_w] + ih_b + hh_b)
    {
        ProbGates p{gbuf, hidden, ih_w, hh_w, ih_b, hh_b, gates, EDIM + HDIM, 2 * HDIM};
        gemm128<ProbGates><<<dim3(2 * HDIM / 128, BATCH / 128), 256>>>(p);
    }
    // 8. t1 = g @ cand_w + cand_b ;  t2 = hidden @ hhc_w + hhc_b
    {
        ProbPlain p{gbuf, cand_w, cand_b, t1, EDIM, HDIM, 0};
        gemm128<ProbPlain><<<dim3(HDIM / 128, BATCH / 128), 256>>>(p);
    }
    {
        ProbPlain p{hidden, hhc_w, hhc_b, t2, HDIM, HDIM, 0};
        gemm128<ProbPlain><<<dim3(HDIM / 128, BATCH / 128), 256>>>(p);
    }
    // 9. GRU combine + LayerNorm -> h output section
    fuse_hln_kernel<<<BATCH, 256>>>(gates, t1, t2, hidden, ln_g, ln_b, out_h);
    // 10. o1 = relu(h @ out1_w + out1_b)
    {
        ProbPlain p{out_h, out1_w, out1_b, o1, HDIM, HDIM, 1};
        gemm128<ProbPlain><<<dim3(HDIM / 128, BATCH / 128), 256>>>(p);
    }
    // 11. logits = o1 @ out2_w + out2_b (guarded N)
    {
        ProbOut2 p{o1, out2_w, out2_b, out_logits, HDIM, VDIM};
        gemm128<ProbOut2><<<dim3((VDIM + 127) / 128, BATCH / 128), 256>>>(p);
    }
    // 12. log_softmax in place
    logsoftmax_kernel<<<BATCH, 512>>>(out_logits);
}

// round 2
// speedup vs baseline: 2.8452x; 2.8452x over previous
#include <cuda_runtime.h>
#include <cstdint>

#define BATCH 256
#define HDIM  1024
#define EDIM  512
#define SDIM  128
#define VDIM  50257

// ---------------- scratch (no allocations allowed) ----------------
__device__ float g_Wh[BATCH * HDIM];
__device__ float g_score[SDIM * BATCH];
__device__ float g_ctx[BATCH * HDIM];
__device__ float g_g[BATCH * EDIM];
__device__ float g_gates[BATCH * 2 * HDIM];
__device__ float g_t1[BATCH * HDIM];
__device__ float g_t2[BATCH * HDIM];
__device__ float g_o1[BATCH * HDIM];

// ---------------- helpers ----------------
__device__ __forceinline__ float warp_sum(float v) {
#pragma unroll
    for (int o = 16; o > 0; o >>= 1) v += __shfl_xor_sync(0xffffffffu, v, o);
    return v;
}
__device__ __forceinline__ float warp_max(float v) {
#pragma unroll
    for (int o = 16; o > 0; o >>= 1) v = fmaxf(v, __shfl_xor_sync(0xffffffffu, v, o));
    return v;
}

__device__ __forceinline__ uint32_t f2tf32(float f) {
    uint32_t u;
    asm("cvt.rna.tf32.f32 %0, %1;" : "=r"(u) : "f"(f));
    return u;
}

__device__ __forceinline__ void mma8(float* c, const uint32_t* a, const uint32_t* b) {
    asm volatile(
        "mma.sync.aligned.m16n8k8.row.col.f32.tf32.tf32.f32 "
        "{%0,%1,%2,%3}, {%4,%5,%6,%7}, {%8,%9}, {%0,%1,%2,%3};"
        : "+f"(c[0]), "+f"(c[1]), "+f"(c[2]), "+f"(c[3])
        : "r"(a[0]), "r"(a[1]), "r"(a[2]), "r"(a[3]), "r"(b[0]), "r"(b[1]));
}

__global__ void zero_kernel(float* p, int n) {
    int i = blockIdx.x * blockDim.x + threadIdx.x;
    if (i < n) p[i] = 0.0f;
}

// =====================================================================
// tf32 tensor-core GEMM template: 128x128 block, 8 warps, warp = 64x32,
// K-tile 16, register-staged prefetch, single smem buffer.
// Functor P: int K; loadA4(r,k)->float4; loadB4(k,c)->float4;
//            store(acc[4][4][4], m0, n0, tid)
// Fragment map (m16n8k8.row.col):
//   row r = m0 + wm*64 + mi*16 + (lane>>2) + 8*(reg>>1)
//   col c = n0 + wn*32 + ni*8  + 2*(lane&3) + (reg&1)
// =====================================================================
template <class P>
__launch_bounds__(256)
__global__ void tgemm(P p) {
    __shared__ uint32_t As[16][136];  // [k][m], pad 136 -> conflict-free frag LDS
    __shared__ uint32_t Bs[16][136];  // [k][n]

    const int tid = threadIdx.x;
    const int lane = tid & 31;
    const int wid = tid >> 5;
    const int wm = wid >> 2, wn = wid & 3;
    const int m0 = blockIdx.y * 128;
    const int n0 = blockIdx.x * 128;

    const int ar = tid >> 1;          // A stage: row 0..127
    const int ak = (tid & 1) * 8;     // A stage: k 0 or 8 (8 k each)
    const int bk = tid >> 5;          // B stage: k 0..7 (and +8)
    const int bc = (tid & 31) * 4;    // B stage: col, float4

    float acc[4][4][4];
#pragma unroll
    for (int i = 0; i < 4; i++)
#pragma unroll
        for (int j = 0; j < 4; j++)
#pragma unroll
            for (int q = 0; q < 4; q++) acc[i][j][q] = 0.0f;

    float4 a0 = p.loadA4(m0 + ar, ak);
    float4 a1 = p.loadA4(m0 + ar, ak + 4);
    float4 b0 = p.loadB4(bk, n0 + bc);
    float4 b1 = p.loadB4(bk + 8, n0 + bc);

    const int KT = p.K >> 4;
    for (int kt = 0; kt < KT; kt++) {
        // stage -> smem (cvt to tf32 once)
        As[ak + 0][ar] = f2tf32(a0.x);
        As[ak + 1][ar] = f2tf32(a0.y);
        As[ak + 2][ar] = f2tf32(a0.z);
        As[ak + 3][ar] = f2tf32(a0.w);
        As[ak + 4][ar] = f2tf32(a1.x);
        As[ak + 5][ar] = f2tf32(a1.y);
        As[ak + 6][ar] = f2tf32(a1.z);
        As[ak + 7][ar] = f2tf32(a1.w);
        uint4 v0, v1;
        v0.x = f2tf32(b0.x); v0.y = f2tf32(b0.y); v0.z = f2tf32(b0.z); v0.w = f2tf32(b0.w);
        v1.x = f2tf32(b1.x); v1.y = f2tf32(b1.y); v1.z = f2tf32(b1.z); v1.w = f2tf32(b1.w);
        *reinterpret_cast<uint4*>(&Bs[bk][bc]) = v0;
        *reinterpret_cast<uint4*>(&Bs[bk + 8][bc]) = v1;
        __syncthreads();

        // prefetch next tile (LDG overlaps MMA below)
        if (kt + 1 < KT) {
            int k0 = (kt + 1) * 16;
            a0 = p.loadA4(m0 + ar, k0 + ak);
            a1 = p.loadA4(m0 + ar, k0 + ak + 4);
            b0 = p.loadB4(k0 + bk, n0 + bc);
            b1 = p.loadB4(k0 + bk + 8, n0 + bc);
        }

#pragma unroll
        for (int k8 = 0; k8 < 16; k8 += 8) {
            uint32_t af[4][4], bf[4][2];
#pragma unroll
            for (int ni = 0; ni < 4; ni++) {
                int nc = wn * 32 + ni * 8 + (lane >> 2);
                bf[ni][0] = Bs[k8 + (lane & 3)][nc];
                bf[ni][1] = Bs[k8 + (lane & 3) + 4][nc];
            }
#pragma unroll
            for (int mi = 0; mi < 4; mi++) {
                int mr = wm * 64 + mi * 16 + (lane >> 2);
                af[mi][0] = As[k8 + (lane & 3)][mr];
                af[mi][1] = As[k8 + (lane & 3)][mr + 8];
                af[mi][2] = As[k8 + (lane & 3) + 4][mr];
                af[mi][3] = As[k8 + (lane & 3) + 4][mr + 8];
            }
#pragma unroll
            for (int mi = 0; mi < 4; mi++)
#pragma unroll
                for (int ni = 0; ni < 4; ni++) mma8(acc[mi][ni], af[mi], bf[ni]);
        }
        __syncthreads();
    }
    p.store(acc, m0, n0, tid);
}

// ---------------- functors ----------------
// act: 0=none, 1=relu, 2=sigmoid
struct ProbPlain {
    const float* A;
    const float* B;
    const float* bias;
    float* C;
    int K;
    int N;
    int act;
    __device__ __forceinline__ float4 loadA4(int r, int k) const {
        return *(const float4*)(A + (size_t)r * K + k);
    }
    __device__ __forceinline__ float4 loadB4(int k, int c) const {
        return *(const float4*)(B + (size_t)k * N + c);
    }
    __device__ __forceinline__ void store(const float (&acc)[4][4][4], int m0, int n0,
                                          int tid) const {
        const int lane = tid & 31, wid = tid >> 5, wm = wid >> 2, wn = wid & 3;
#pragma unroll
        for (int mi = 0; mi < 4; mi++) {
            int r = m0 + wm * 64 + mi * 16 + (lane >> 2);
#pragma unroll
            for (int ni = 0; ni < 4; ni++) {
                int c = n0 + wn * 32 + ni * 8 + (lane & 3) * 2;
                float bx = bias[c], by = bias[c + 1];
                float2 lo = make_float2(acc[mi][ni][0] + bx, acc[mi][ni][1] + by);
                float2 hi = make_float2(acc[mi][ni][2] + bx, acc[mi][ni][3] + by);
                if (act == 1) {
                    lo.x = fmaxf(lo.x, 0.f); lo.y = fmaxf(lo.y, 0.f);
                    hi.x = fmaxf(hi.x, 0.f); hi.y = fmaxf(hi.y, 0.f);
                } else if (act == 2) {
                    lo.x = 1.f / (1.f + expf(-lo.x)); lo.y = 1.f / (1.f + expf(-lo.y));
                    hi.x = 1.f / (1.f + expf(-hi.x)); hi.y = 1.f / (1.f + expf(-hi.y));
                }
                *(float2*)(C + (size_t)r * N + c) = lo;
                *(float2*)(C + (size_t)(r + 8) * N + c) = hi;
            }
        }
    }
};

// g = relu([emb[ids], ctx] @ comb_w + comb_b), K=1536, N=512
struct ProbComb {
    const float* emb;
    const int* ids;
    const float* ctx;
    const float* B;
    const float* bias;
    float* C;
    int K;
    int N;
    __device__ __forceinline__ float4 loadA4(int r, int k) const {
        if (k < EDIM) return *(const float4*)(emb + (size_t)__ldg(&ids[r]) * EDIM + k);
        return *(const float4*)(ctx + (size_t)r * HDIM + (k - EDIM));
    }
    __device__ __forceinline__ float4 loadB4(int k, int c) const {
        return *(const float4*)(B + (size_t)k * N + c);
    }
    __device__ __forceinline__ void store(const float (&acc)[4][4][4], int m0, int n0,
                                          int tid) const {
        const int lane = tid & 31, wid = tid >> 5, wm = wid >> 2, wn = wid & 3;
#pragma unroll
        for (int mi = 0; mi < 4; mi++) {
            int r = m0 + wm * 64 + mi * 16 + (lane >> 2);
#pragma unroll
            for (int ni = 0; ni < 4; ni++) {
                int c = n0 + wn * 32 + ni * 8 + (lane & 3) * 2;
                float bx = bias[c], by = bias[c + 1];
                float2 lo = make_float2(fmaxf(acc[mi][ni][0] + bx, 0.f),
                                        fmaxf(acc[mi][ni][1] + by, 0.f));
                float2 hi = make_float2(fmaxf(acc[mi][ni][2] + bx, 0.f),
                                        fmaxf(acc[mi][ni][3] + by, 0.f));
                *(float2*)(C + (size_t)r * N + c) = lo;
                *(float2*)(C + (size_t)(r + 8) * N + c) = hi;
            }
        }
    }
};

// gates = sigmoid([g, hidden] @ [ih_w; hh_w] + ih_b + hh_b), K=1536, N=2048
struct ProbGates {
    const float* gA;
    const float* hid;
    const float* ihw;
    const float* hhw;
    const float* ihb;
    const float* hhb;
    float* C;
    int K;
    int N;
    __device__ __forceinline__ float4 loadA4(int r, int k) const {
        if (k < EDIM) return *(const float4*)(gA + (size_t)r * EDIM + k);
        return *(const float4*)(hid + (size_t)r * HDIM + (k - EDIM));
    }
    __device__ __forceinline__ float4 loadB4(int k, int c) const {
        if (k < EDIM) return *(const float4*)(ihw + (size_t)k * N + c);
        return *(const float4*)(hhw + (size_t)(k - EDIM) * N + c);
    }
    __device__ __forceinline__ void store(const float (&acc)[4][4][4], int m0, int n0,
                                          int tid) const {
        const int lane = tid & 31, wid = tid >> 5, wm = wid >> 2, wn = wid & 3;
#pragma unroll
        for (int mi = 0; mi < 4; mi++) {
            int r = m0 + wm * 64 + mi * 16 + (lane >> 2);
#pragma unroll
            for (int ni = 0; ni < 4; ni++) {
                int c = n0 + wn * 32 + ni * 8 + (lane & 3) * 2;
                float bx = ihb[c] + hhb[c], by = ihb[c + 1] + hhb[c + 1];
                float2 lo, hi;
                lo.x = 1.f / (1.f + expf(-(acc[mi][ni][0] + bx)));
                lo.y = 1.f / (1.f + expf(-(acc[mi][ni][1] + by)));
                hi.x = 1.f / (1.f + expf(-(acc[mi][ni][2] + bx)));
                hi.y = 1.f / (1.f + expf(-(acc[mi][ni][3] + by)));
                *(float2*)(C + (size_t)r * N + c) = lo;
                *(float2*)(C + (size_t)(r + 8) * N + c) = hi;
            }
        }
    }
};

// logits = o1 @ out2_w + out2_b ; N=50257 (odd) -> scalar guarded B loads/stores
struct ProbOut2 {
    const float* A;
    const float* B;
    const float* bias;
    float* C;
    int K;
    int N;
    __device__ __forceinline__ float4 loadA4(int r, int k) const {
        return *(const float4*)(A + (size_t)r * K + k);
    }
    __device__ __forceinline__ float4 loadB4(int k, int c) const {
        const float* p = B + (size_t)k * N;
        float4 v;
        v.x = (c + 0 < N) ? __ldg(p + c + 0) : 0.0f;
        v.y = (c + 1 < N) ? __ldg(p + c + 1) : 0.0f;
        v.z = (c + 2 < N) ? __ldg(p + c + 2) : 0.0f;
        v.w = (c + 3 < N) ? __ldg(p + c + 3) : 0.0f;
        return v;
    }
    __device__ __forceinline__ void store(const float (&acc)[4][4][4], int m0, int n0,
                                          int tid) const {
        const int lane = tid & 31, wid = tid >> 5, wm = wid >> 2, wn = wid & 3;
#pragma unroll
        for (int mi = 0; mi < 4; mi++) {
            int r = m0 + wm * 64 + mi * 16 + (lane >> 2);
#pragma unroll
            for (int ni = 0; ni < 4; ni++) {
                int c = n0 + wn * 32 + ni * 8 + (lane & 3) * 2;
#pragma unroll
                for (int q = 0; q < 4; q++) {
                    int cc = c + (q & 1);
                    int rr = r + (q >> 1) * 8;
                    if (cc < N) C[(size_t)rr * N + cc] = acc[mi][ni][q] + bias[cc];
                }
            }
        }
    }
};

// score[m] += sum_c tanh(enc@U_w[m,c] + Wh[m&255,c] + U_b[c]) * v_w[c]
struct ProbScore {
    const float* A;   // enc (S*N, H)
    const float* B;   // U_w (H, H)
    const float* Wh;
    const float* Ub;
    const float* vw;
    float* score;
    int K;
    __device__ __forceinline__ float4 loadA4(int r, int k) const {
        return *(const float4*)(A + (size_t)r * HDIM + k);
    }
    __device__ __forceinline__ float4 loadB4(int k, int c) const {
        return *(const float4*)(B + (size_t)k * HDIM + c);
    }
    __device__ __forceinline__ void store(const float (&acc)[4][4][4], int m0, int n0,
                                          int tid) const {
        __shared__ float red[4][128];
        const int lane = tid & 31, wid = tid >> 5, wm = wid >> 2, wn = wid & 3;
#pragma unroll
        for (int mi = 0; mi < 4; mi++) {
            int r0 = m0 + wm * 64 + mi * 16 + (lane >> 2);
            const float* wh0 = Wh + (size_t)(r0 & (BATCH - 1)) * HDIM;
            const float* wh1 = Wh + (size_t)((r0 + 8) & (BATCH - 1)) * HDIM;
            float s0 = 0.f, s1 = 0.f;
#pragma unroll
            for (int ni = 0; ni < 4; ni++) {
                int c = n0 + wn * 32 + ni * 8 + (lane & 3) * 2;
                float u0 = Ub[c], u1 = Ub[c + 1];
                float w0 = vw[c], w1 = vw[c + 1];
                s0 += tanhf(acc[mi][ni][0] + wh0[c] + u0) * w0;
                s0 += tanhf(acc[mi][ni][1] + wh0[c + 1] + u1) * w1;
                s1 += tanhf(acc[mi][ni][2] + wh1[c] + u0) * w0;
                s1 += tanhf(acc[mi][ni][3] + wh1[c + 1] + u1) * w1;
            }
            s0 += __shfl_xor_sync(0xffffffffu, s0, 1);
            s0 += __shfl_xor_sync(0xffffffffu, s0, 2);
            s1 += __shfl_xor_sync(0xffffffffu, s1, 1);
            s1 += __shfl_xor_sync(0xffffffffu, s1, 2);
            if ((lane & 3) == 0) {
                red[wn][wm * 64 + mi * 16 + (lane >> 2)] = s0;
                red[wn][wm * 64 + mi * 16 + (lane >> 2) + 8] = s1;
            }
        }
        __syncthreads();
        if (tid < 128)
            atomicAdd(&score[m0 + tid],
                      red[0][tid] + red[1][tid] + red[2][tid] + red[3][tid]);
    }
};

// ---------------- softmax over S (axis 0) -> attn ----------------
__global__ void softmax_kernel(const float* __restrict__ score,
                               float* __restrict__ attn_out) {
    const int n = blockIdx.x;
    const int s = threadIdx.x;  // 128
    float v = score[s * BATCH + n];
    __shared__ float rmax[4], rsum[4];
    float m = warp_max(v);
    if ((s & 31) == 0) rmax[s >> 5] = m;
    __syncthreads();
    m = fmaxf(fmaxf(rmax[0], rmax[1]), fmaxf(rmax[2], rmax[3]));
    float e = expf(v - m);
    float t = warp_sum(e);
    if ((s & 31) == 0) rsum[s >> 5] = t;
    __syncthreads();
    float sum = rsum[0] + rsum[1] + rsum[2] + rsum[3];
    attn_out[s * BATCH + n] = e / sum;
}

// ---------------- context ----------------
__global__ void context_kernel(const float* __restrict__ enc,
                               const float* __restrict__ attn,
                               float* __restrict__ ctx) {
    const int n = blockIdx.x;
    const int tid = threadIdx.x;  // 256
    __shared__ float a[SDIM];
    if (tid < SDIM) a[tid] = attn[tid * BATCH + n];
    __syncthreads();
    float4 acc = make_float4(0.f, 0.f, 0.f, 0.f);
    for (int s = 0; s < SDIM; s++) {
        float4 e = ((const float4*)(enc + ((size_t)s * BATCH + n) * HDIM))[tid];
        float w = a[s];
        acc.x = fmaf(w, e.x, acc.x);
        acc.y = fmaf(w, e.y, acc.y);
        acc.z = fmaf(w, e.z, acc.z);
        acc.w = fmaf(w, e.w, acc.w);
    }
    ((float4*)(ctx + (size_t)n * HDIM))[tid] = acc;
}

// ---------------- GRU combine + LayerNorm ----------------
__global__ void fuse_hln_kernel(const float* __restrict__ gates,
                                const float* __restrict__ t1,
                                const float* __restrict__ t2,
                                const float* __restrict__ hid,
                                const float* __restrict__ lng,
                                const float* __restrict__ lnb,
                                float* __restrict__ hout) {
    const int n = blockIdx.x;
    const int tid = threadIdx.x;  // 256
    float4 z = ((const float4*)(gates + (size_t)n * 2 * HDIM))[tid];
    float4 r = ((const float4*)(gates + (size_t)n * 2 * HDIM + HDIM))[tid];
    float4 a = ((const float4*)(t1 + (size_t)n * HDIM))[tid];
    float4 b = ((const float4*)(t2 + (size_t)n * HDIM))[tid];
    float4 hv = ((const float4*)(hid + (size_t)n * HDIM))[tid];
    float4 hr;
    hr.x = (1.0f - z.x) * hv.x + z.x * tanhf(a.x + r.x * b.x);
    hr.y = (1.0f - z.y) * hv.y + z.y * tanhf(a.y + r.y * b.y);
    hr.z = (1.0f - z.z) * hv.z + z.z * tanhf(a.z + r.z * b.z);
    hr.w = (1.0f - z.w) * hv.w + z.w * tanhf(a.w + r.w * b.w);
    float s = hr.x + hr.y + hr.z + hr.w;
    float ss = hr.x * hr.x + hr.y * hr.y + hr.z * hr.z + hr.w * hr.w;
    __shared__ float sm1[8], sm2[8];
    float w1 = warp_sum(s), w2 = warp_sum(ss);
    if ((tid & 31) == 0) { sm1[tid >> 5] = w1; sm2[tid >> 5] = w2; }
    __syncthreads();
    float tot1 = 0.f, tot2 = 0.f;
#pragma unroll
    for (int q = 0; q < 8; q++) { tot1 += sm1[q]; tot2 += sm2[q]; }
    float mu = tot1 * (1.0f / HDIM);
    float var = tot2 * (1.0f / HDIM) - mu * mu;
    float inv = rsqrtf(var + 1e-5f);
    float4 gg = ((const float4*)lng)[tid];
    float4 bb = ((const float4*)lnb)[tid];
    float4 o;
    o.x = (hr.x - mu) * inv * gg.x + bb.x;
    o.y = (hr.y - mu) * inv * gg.y + bb.y;
    o.z = (hr.z - mu) * inv * gg.z + bb.z;
    o.w = (hr.w - mu) * inv * gg.w + bb.w;
    ((float4*)(hout + (size_t)n * HDIM))[tid] = o;
}

// ---------------- log_softmax in place ----------------
__global__ void logsoftmax_kernel(float* __restrict__ logits) {
    const int n = blockIdx.x;
    const int tid = threadIdx.x;  // 512
    float* row = logits + (size_t)n * VDIM;
    __shared__ float sm[16];
    float m = -3.4e38f;
    for (int i = tid; i < VDIM; i += 512) m = fmaxf(m, row[i]);
    m = warp_max(m);
    if ((tid & 31) == 0) sm[tid >> 5] = m;
    __syncthreads();
    float mx = -3.4e38f;
#pragma unroll
    for (int q = 0; q < 16; q++) mx = fmaxf(mx, sm[q]);
    __syncthreads();
    float s = 0.0f;
    for (int i = tid; i < VDIM; i += 512) s += expf(row[i] - mx);
    s = warp_sum(s);
    if ((tid & 31) == 0) sm[tid >> 5] = s;
    __syncthreads();
    float tot = 0.0f;
#pragma unroll
    for (int q = 0; q < 16; q++) tot += sm[q];
    float lse = mx + logf(tot);
    for (int i = tid; i < VDIM; i += 512) row[i] = row[i] - lse;
}

// ---------------- launch ----------------
extern "C" void kernel_launch(void* const* d_in, const int* in_sizes, int n_in,
                              void* d_out, int out_size) {
    const int* ids = (const int*)d_in[0];
    const float* hidden = (const float*)d_in[1];
    const float* enc = (const float*)d_in[2];
    const float* emb = (const float*)d_in[3];
    const float* W_w = (const float*)d_in[4];
    const float* W_b = (const float*)d_in[5];
    const float* U_w = (const float*)d_in[6];
    const float* U_b = (const float*)d_in[7];
    const float* v_w = (const float*)d_in[8];
    // d_in[9] = v_b : constant over S, cancels in softmax
    const float* ih_w = (const float*)d_in[10];
    const float* ih_b = (const float*)d_in[11];
    const float* hh_w = (const float*)d_in[12];
    const float* hh_b = (const float*)d_in[13];
    const float* cand_w = (const float*)d_in[14];
    const float* cand_b = (const float*)d_in[15];
    const float* hhc_w = (const float*)d_in[16];
    const float* hhc_b = (const float*)d_in[17];
    const float* comb_w = (const float*)d_in[18];
    const float* comb_b = (const float*)d_in[19];
    const float* ln_g = (const float*)d_in[20];
    const float* ln_b = (const float*)d_in[21];
    const float* out1_w = (const float*)d_in[22];
    const float* out1_b = (const float*)d_in[23];
    const float* out2_w = (const float*)d_in[24];
    const float* out2_b = (const float*)d_in[25];

    float* out_logits = (float*)d_out;
    float* out_h = out_logits + (size_t)BATCH * VDIM;
    float* out_attn = out_h + (size_t)BATCH * HDIM;

    float *Wh, *score, *ctx, *gbuf, *gates, *t1, *t2, *o1;
    cudaGetSymbolAddress((void**)&Wh, g_Wh);
    cudaGetSymbolAddress((void**)&score, g_score);
    cudaGetSymbolAddress((void**)&ctx, g_ctx);
    cudaGetSymbolAddress((void**)&gbuf, g_g);
    cudaGetSymbolAddress((void**)&gates, g_gates);
    cudaGetSymbolAddress((void**)&t1, g_t1);
    cudaGetSymbolAddress((void**)&t2, g_t2);
    cudaGetSymbolAddress((void**)&o1, g_o1);

    // 1. Wh = hidden @ W_w + W_b
    {
        ProbPlain p{hidden, W_w, W_b, Wh, HDIM, HDIM, 0};
        tgemm<ProbPlain><<<dim3(HDIM / 128, BATCH / 128), 256>>>(p);
    }
    // 2. zero score
    zero_kernel<<<(SDIM * BATCH + 255) / 256, 256>>>(score, SDIM * BATCH);
    // 3. fused score GEMM (tensor core)
    {
        ProbScore p{enc, U_w, Wh, U_b, v_w, score, HDIM};
        tgemm<ProbScore><<<dim3(HDIM / 128, (SDIM * BATCH) / 128), 256>>>(p);
    }
    // 4. softmax -> attn output
    softmax_kernel<<<BATCH, SDIM>>>(score, out_attn);
    // 5. context
    context_kernel<<<BATCH, 256>>>(enc, out_attn, ctx);
    // 6. g
    {
        ProbComb p{emb, ids, ctx, comb_w, comb_b, gbuf, EDIM + HDIM, EDIM};
        tgemm<ProbComb><<<dim3(EDIM / 128, BATCH / 128), 256>>>(p);
    }
    // 7. gates
    {
        ProbGates p{gbuf, hidden, ih_w, hh_w, ih_b, hh_b, gates, EDIM + HDIM, 2 * HDIM};
        tgemm<ProbGates><<<dim3(2 * HDIM / 128, BATCH / 128), 256>>>(p);
    }
    // 8. t1, t2
    {
        ProbPlain p{gbuf, cand_w, cand_b, t1, EDIM, HDIM, 0};
        tgemm<ProbPlain><<<dim3(HDIM / 128, BATCH / 128), 256>>>(p);
    }
    {
        ProbPlain p{hidden, hhc_w, hhc_b, t2, HDIM, HDIM, 0};
        tgemm<ProbPlain><<<dim3(HDIM / 128, BATCH / 128), 256>>>(p);
    }
    // 9. GRU combine + LayerNorm
    fuse_hln_kernel<<<BATCH, 256>>>(gates, t1, t2, hidden, ln_g, ln_b, out_h);
    // 10. o1 = relu(h @ out1_w + out1_b)
    {
        ProbPlain p{out_h, out1_w, out1_b, o1, HDIM, HDIM, 1};
        tgemm<ProbPlain><<<dim3(HDIM / 128, BATCH / 128), 256>>>(p);
    }
    // 11. logits
    {
        ProbOut2 p{o1, out2_w, out2_b, out_logits, HDIM, VDIM};
        tgemm<ProbOut2><<<dim3((VDIM + 127) / 128, BATCH / 128), 256>>>(p);
    }
    // 12. log_softmax
    logsoftmax_kernel<<<BATCH, 512>>>(out_logits);
}

// round 3
// speedup vs baseline: 3.8238x; 1.3439x over previous
#include <cuda_runtime.h>
#include <cstdint>

#define BATCH 256
#define HDIM  1024
#define EDIM  512
#define SDIM  128
#define VDIM  50257

// ---------------- scratch (no allocations allowed) ----------------
__device__ float g_Wh[BATCH * HDIM];
__device__ float g_score[SDIM * BATCH];
__device__ float g_ctx[BATCH * HDIM];
__device__ float g_g[BATCH * EDIM];
__device__ float g_gates[BATCH * 2 * HDIM];
__device__ float g_t1[BATCH * HDIM];
__device__ float g_t2[BATCH * HDIM];
__device__ float g_o1[BATCH * HDIM];

// ---------------- helpers ----------------
__device__ __forceinline__ float warp_sum(float v) {
#pragma unroll
    for (int o = 16; o > 0; o >>= 1) v += __shfl_xor_sync(0xffffffffu, v, o);
    return v;
}
__device__ __forceinline__ float warp_max(float v) {
#pragma unroll
    for (int o = 16; o > 0; o >>= 1) v = fmaxf(v, __shfl_xor_sync(0xffffffffu, v, o));
    return v;
}

__device__ __forceinline__ void mma8(float* c, const uint32_t* a, const uint32_t* b) {
    asm volatile(
        "mma.sync.aligned.m16n8k8.row.col.f32.tf32.tf32.f32 "
        "{%0,%1,%2,%3}, {%4,%5,%6,%7}, {%8,%9}, {%0,%1,%2,%3};"
        : "+f"(c[0]), "+f"(c[1]), "+f"(c[2]), "+f"(c[3])
        : "r"(a[0]), "r"(a[1]), "r"(a[2]), "r"(a[3]), "r"(b[0]), "r"(b[1]));
}

__device__ __forceinline__ void cpa16(void* smem_dst, const void* gsrc) {
    uint32_t d = (uint32_t)__cvta_generic_to_shared(smem_dst);
    asm volatile("cp.async.ca.shared.global [%0], [%1], 16;" ::"r"(d), "l"(gsrc));
}
__device__ __forceinline__ void cpa16z(void* smem_dst, const void* gsrc, int srcsz) {
    uint32_t d = (uint32_t)__cvta_generic_to_shared(smem_dst);
    asm volatile("cp.async.ca.shared.global [%0], [%1], 16, %2;" ::"r"(d), "l"(gsrc),
                 "r"(srcsz));
}
__device__ __forceinline__ void cpa4z(void* smem_dst, const void* gsrc, int srcsz) {
    uint32_t d = (uint32_t)__cvta_generic_to_shared(smem_dst);
    asm volatile("cp.async.ca.shared.global [%0], [%1], 4, %2;" ::"r"(d), "l"(gsrc),
                 "r"(srcsz));
}
__device__ __forceinline__ void cpa_commit() {
    asm volatile("cp.async.commit_group;");
}
__device__ __forceinline__ void cpa_wait1() {
    asm volatile("cp.async.wait_group 1;");
}

__global__ void zero_kernel(float* p, int n) {
    int i = blockIdx.x * blockDim.x + threadIdx.x;
    if (i < n) p[i] = 0.0f;
}

// =====================================================================
// tf32 tensor-core GEMM, cp.async double-buffered.
// 128x128 block, 8 warps (warp=64x32, 4x4 mma grid), K-tile 16.
// As: [stage][m:128][k:20pad]  Bs: [stage][k:16][n:136pad]
// Functor P: int K; aChunk(r,k)->const float* (16B chunk);
//            copyB(bs, n0, k0, tid); store(acc, m0, n0, tid)
// fp32 bits fed straight to tf32 mma (HW truncation).
// =====================================================================
template <class P>
__launch_bounds__(256)
__global__ void tgemm(P p) {
    __shared__ float As[2][128][20];
    __shared__ float Bs[2][16][136];

    const int tid = threadIdx.x;
    const int lane = tid & 31, wid = tid >> 5;
    const int wm = wid >> 2, wn = wid & 3;
    const int q = lane >> 2, t = lane & 3;
    const int m0 = blockIdx.y * 128;
    const int n0 = blockIdx.x * 128;

    float acc[4][4][4];
#pragma unroll
    for (int i = 0; i < 4; i++)
#pragma unroll
        for (int j = 0; j < 4; j++)
#pragma unroll
            for (int r = 0; r < 4; r++) acc[i][j][r] = 0.0f;

    auto copyA = [&](int st, int k0) {
#pragma unroll
        for (int i = 0; i < 2; i++) {
            int c = tid + i * 256;          // 512 chunks: 128 rows x 4
            int row = c >> 2, kp = (c & 3) << 2;
            cpa16(&As[st][row][kp], p.aChunk(m0 + row, k0 + kp));
        }
    };

    const int KT = p.K >> 4;
    copyA(0, 0);
    p.copyB(&Bs[0][0][0], n0, 0, tid);
    cpa_commit();
    copyA(1, 16);
    p.copyB(&Bs[1][0][0], n0, 16, tid);
    cpa_commit();

    for (int kt = 0; kt < KT; kt++) {
        cpa_wait1();
        __syncthreads();
        const int st = kt & 1;

#pragma unroll
        for (int k8 = 0; k8 < 16; k8 += 8) {
            uint32_t af[4][4], bf[4][2];
#pragma unroll
            for (int ni = 0; ni < 4; ni++) {
                int nc = wn * 32 + ni * 8 + q;
                bf[ni][0] = __float_as_uint(Bs[st][k8 + t][nc]);
                bf[ni][1] = __float_as_uint(Bs[st][k8 + t + 4][nc]);
            }
#pragma unroll
            for (int mi = 0; mi < 4; mi++) {
                int mr = wm * 64 + mi * 16 + q;
                af[mi][0] = __float_as_uint(As[st][mr][k8 + t]);
                af[mi][1] = __float_as_uint(As[st][mr + 8][k8 + t]);
                af[mi][2] = __float_as_uint(As[st][mr][k8 + t + 4]);
                af[mi][3] = __float_as_uint(As[st][mr + 8][k8 + t + 4]);
            }
#pragma unroll
            for (int mi = 0; mi < 4; mi++)
#pragma unroll
                for (int ni = 0; ni < 4; ni++) mma8(acc[mi][ni], af[mi], bf[ni]);
        }
        __syncthreads();
        if (kt + 2 < KT) {
            copyA(st, (kt + 2) * 16);
            p.copyB(&Bs[st][0][0], n0, (kt + 2) * 16, tid);
        }
        cpa_commit();
    }
    p.store(acc, m0, n0, tid);
}

// standard dense-B copier: 512 x 16B chunks, row stride N
__device__ __forceinline__ void copyB_dense(float* bs, const float* B, int ldb, int n0,
                                            int k0, int tid) {
#pragma unroll
    for (int i = 0; i < 2; i++) {
        int c = tid + i * 256;
        int k = c >> 5, np = (c & 31) << 2;
        cpa16(bs + k * 136 + np, B + (size_t)(k0 + k) * ldb + n0 + np);
    }
}

// ---------------- functors ----------------
// act: 0=none, 1=relu
struct ProbPlain {
    const float* A;
    const float* B;
    const float* bias;
    float* C;
    int K;
    int N;
    int act;
    __device__ __forceinline__ const float* aChunk(int r, int k) const {
        return A + (size_t)r * K + k;
    }
    __device__ __forceinline__ void copyB(float* bs, int n0, int k0, int tid) const {
        copyB_dense(bs, B, N, n0, k0, tid);
    }
    __device__ __forceinline__ void store(const float (&acc)[4][4][4], int m0, int n0,
                                          int tid) const {
        const int lane = tid & 31, wid = tid >> 5, wm = wid >> 2, wn = wid & 3;
#pragma unroll
        for (int mi = 0; mi < 4; mi++) {
            int r = m0 + wm * 64 + mi * 16 + (lane >> 2);
#pragma unroll
            for (int ni = 0; ni < 4; ni++) {
                int c = n0 + wn * 32 + ni * 8 + (lane & 3) * 2;
                float bx = bias[c], by = bias[c + 1];
                float2 lo = make_float2(acc[mi][ni][0] + bx, acc[mi][ni][1] + by);
                float2 hi = make_float2(acc[mi][ni][2] + bx, acc[mi][ni][3] + by);
                if (act == 1) {
                    lo.x = fmaxf(lo.x, 0.f);
                    lo.y = fmaxf(lo.y, 0.f);
                    hi.x = fmaxf(hi.x, 0.f);
                    hi.y = fmaxf(hi.y, 0.f);
                }
                *(float2*)(C + (size_t)r * N + c) = lo;
                *(float2*)(C + (size_t)(r + 8) * N + c) = hi;
            }
        }
    }
};

// g = relu([emb[ids], ctx] @ comb_w + comb_b), K=1536, N=512
struct ProbComb {
    const float* emb;
    const int* ids;
    const float* ctx;
    const float* B;
    const float* bias;
    float* C;
    int K;
    __device__ __forceinline__ const float* aChunk(int r, int k) const {
        if (k < EDIM) return emb + (size_t)__ldg(&ids[r]) * EDIM + k;
        return ctx + (size_t)r * HDIM + (k - EDIM);
    }
    __device__ __forceinline__ void copyB(float* bs, int n0, int k0, int tid) const {
        copyB_dense(bs, B, EDIM, n0, k0, tid);
    }
    __device__ __forceinline__ void store(const float (&acc)[4][4][4], int m0, int n0,
                                          int tid) const {
        const int lane = tid & 31, wid = tid >> 5, wm = wid >> 2, wn = wid & 3;
        const int N = EDIM;
#pragma unroll
        for (int mi = 0; mi < 4; mi++) {
            int r = m0 + wm * 64 + mi * 16 + (lane >> 2);
#pragma unroll
            for (int ni = 0; ni < 4; ni++) {
                int c = n0 + wn * 32 + ni * 8 + (lane & 3) * 2;
                float bx = bias[c], by = bias[c + 1];
                float2 lo = make_float2(fmaxf(acc[mi][ni][0] + bx, 0.f),
                                        fmaxf(acc[mi][ni][1] + by, 0.f));
                float2 hi = make_float2(fmaxf(acc[mi][ni][2] + bx, 0.f),
                                        fmaxf(acc[mi][ni][3] + by, 0.f));
                *(float2*)(C + (size_t)r * N + c) = lo;
                *(float2*)(C + (size_t)(r + 8) * N + c) = hi;
            }
        }
    }
};

// Fused gates|t1|t2.  A=[g(512), hidden(1024)] K=1536.
// B columns: [0,2048): [ih_w;hh_w] -> sigmoid -> gates(2048)
//            [2048,3072): [cand_w;0] -> +cand_b -> t1(1024)
//            [3072,4096): [0;hhc_w] -> +hhc_b -> t2(1024)
struct ProbFused3 {
    const float* g;
    const float* hid;
    const float* ihw;
    const float* hhw;
    const float* candw;
    const float* hhcw;
    const float* ihb;
    const float* hhb;
    const float* candb;
    const float* hhcb;
    float* Cg;
    float* Ct1;
    float* Ct2;
    int K;
    __device__ __forceinline__ const float* aChunk(int r, int k) const {
        if (k < EDIM) return g + (size_t)r * EDIM + k;
        return hid + (size_t)r * HDIM + (k - EDIM);
    }
    __device__ __forceinline__ void copyB(float* bs, int n0, int k0, int tid) const {
#pragma unroll
        for (int i = 0; i < 2; i++) {
            int c = tid + i * 256;
            int k = c >> 5, np = (c & 31) << 2;
            int gk = k0 + k, gc = n0 + np;
            const float* src = ihw;  // valid dummy for zfill
            int sz = 16;
            if (gc < 2048) {
                src = (gk < EDIM) ? ihw + (size_t)gk * 2048 + gc
                                  : hhw + (size_t)(gk - EDIM) * 2048 + gc;
            } else if (gc < 3072) {
                if (gk < EDIM) src = candw + (size_t)gk * HDIM + (gc - 2048);
                else sz = 0;
            } else {
                if (gk >= EDIM) src = hhcw + (size_t)(gk - EDIM) * HDIM + (gc - 3072);
                else sz = 0;
            }
            cpa16z(bs + k * 136 + np, src, sz);
        }
    }
    __device__ __forceinline__ void store(const float (&acc)[4][4][4], int m0, int n0,
                                          int tid) const {
        const int lane = tid & 31, wid = tid >> 5, wm = wid >> 2, wn = wid & 3;
        // whole block lies in one region (boundaries are multiples of 128)
        float* C;
        const float* b0p;
        const float* b1p;
        int N, cbase, sig;
        if (n0 < 2048) {
            C = Cg; N = 2048; cbase = n0; b0p = ihb; b1p = hhb; sig = 1;
        } else if (n0 < 3072) {
            C = Ct1; N = HDIM; cbase = n0 - 2048; b0p = candb; b1p = nullptr; sig = 0;
        } else {
            C = Ct2; N = HDIM; cbase = n0 - 3072; b0p = hhcb; b1p = nullptr; sig = 0;
        }
#pragma unroll
        for (int mi = 0; mi < 4; mi++) {
            int r = m0 + wm * 64 + mi * 16 + (lane >> 2);
#pragma unroll
            for (int ni = 0; ni < 4; ni++) {
                int c = cbase + wn * 32 + ni * 8 + (lane & 3) * 2;
                float bx = b0p[c], by = b0p[c + 1];
                if (b1p) { bx += b1p[c]; by += b1p[c + 1]; }
                float2 lo = make_float2(acc[mi][ni][0] + bx, acc[mi][ni][1] + by);
                float2 hi = make_float2(acc[mi][ni][2] + bx, acc[mi][ni][3] + by);
                if (sig) {
                    lo.x = 1.f / (1.f + expf(-lo.x));
                    lo.y = 1.f / (1.f + expf(-lo.y));
                    hi.x = 1.f / (1.f + expf(-hi.x));
                    hi.y = 1.f / (1.f + expf(-hi.y));
                }
                *(float2*)(C + (size_t)r * N + c) = lo;
                *(float2*)(C + (size_t)(r + 8) * N + c) = hi;
            }
        }
    }
};

// logits = o1 @ out2_w + out2_b ; N=50257 (odd rows) -> 4B zfill cp.async
struct ProbOut2 {
    const float* A;
    const float* B;
    const float* bias;
    float* C;
    int K;
    int N;
    __device__ __forceinline__ const float* aChunk(int r, int k) const {
        return A + (size_t)r * K + k;
    }
    __device__ __forceinline__ void copyB(float* bs, int n0, int k0, int tid) const {
#pragma unroll
        for (int i = 0; i < 8; i++) {
            int e = tid + i * 256;  // 2048 floats
            int k = e >> 7, n = e & 127;
            int gn = n0 + n;
            int ok = gn < N;
            const float* src = B + (size_t)(k0 + k) * N + (ok ? gn : 0);
            cpa4z(bs + k * 136 + n, src, ok ? 4 : 0);
        }
    }
    __device__ __forceinline__ void store(const float (&acc)[4][4][4], int m0, int n0,
                                          int tid) const {
        const int lane = tid & 31, wid = tid >> 5, wm = wid >> 2, wn = wid & 3;
#pragma unroll
        for (int mi = 0; mi < 4; mi++) {
            int r = m0 + wm * 64 + mi * 16 + (lane >> 2);
#pragma unroll
            for (int ni = 0; ni < 4; ni++) {
                int c = n0 + wn * 32 + ni * 8 + (lane & 3) * 2;
#pragma unroll
                for (int rr = 0; rr < 4; rr++) {
                    int cc = c + (rr & 1);
                    int rrr = r + (rr >> 1) * 8;
                    if (cc < N) C[(size_t)rrr * N + cc] = acc[mi][ni][rr] + bias[cc];
                }
            }
        }
    }
};

// score[m] += sum_c tanh(enc@U_w[m,c] + Wh[m&255,c] + U_b[c]) * v_w[c]
struct ProbScore {
    const float* enc;
    const float* Uw;
    const float* Wh;
    const float* Ub;
    const float* vw;
    float* score;
    int K;
    __device__ __forceinline__ const float* aChunk(int r, int k) const {
        return enc + (size_t)r * HDIM + k;
    }
    __device__ __forceinline__ void copyB(float* bs, int n0, int k0, int tid) const {
        copyB_dense(bs, Uw, HDIM, n0, k0, tid);
    }
    __device__ __forceinline__ void store(const float (&acc)[4][4][4], int m0, int n0,
                                          int tid) const {
        __shared__ float red[4][128];
        const int lane = tid & 31, wid = tid >> 5, wm = wid >> 2, wn = wid & 3;
#pragma unroll
        for (int mi = 0; mi < 4; mi++) {
            int r0 = m0 + wm * 64 + mi * 16 + (lane >> 2);
            const float* wh0 = Wh + (size_t)(r0 & (BATCH - 1)) * HDIM;
            const float* wh1 = Wh + (size_t)((r0 + 8) & (BATCH - 1)) * HDIM;
            float s0 = 0.f, s1 = 0.f;
#pragma unroll
            for (int ni = 0; ni < 4; ni++) {
                int c = n0 + wn * 32 + ni * 8 + (lane & 3) * 2;
                float u0 = Ub[c], u1 = Ub[c + 1];
                float w0 = vw[c], w1 = vw[c + 1];
                s0 += tanhf(acc[mi][ni][0] + wh0[c] + u0) * w0;
                s0 += tanhf(acc[mi][ni][1] + wh0[c + 1] + u1) * w1;
                s1 += tanhf(acc[mi][ni][2] + wh1[c] + u0) * w0;
                s1 += tanhf(acc[mi][ni][3] + wh1[c + 1] + u1) * w1;
            }
            s0 += __shfl_xor_sync(0xffffffffu, s0, 1);
            s0 += __shfl_xor_sync(0xffffffffu, s0, 2);
            s1 += __shfl_xor_sync(0xffffffffu, s1, 1);
            s1 += __shfl_xor_sync(0xffffffffu, s1, 2);
            if ((lane & 3) == 0) {
                red[wn][wm * 64 + mi * 16 + (lane >> 2)] = s0;
                red[wn][wm * 64 + mi * 16 + (lane >> 2) + 8] = s1;
            }
        }
        __syncthreads();
        if (tid < 128)
            atomicAdd(&score[m0 + tid],
                      red[0][tid] + red[1][tid] + red[2][tid] + red[3][tid]);
    }
};

// ---------------- softmax over S (axis 0) -> attn ----------------
__global__ void softmax_kernel(const float* __restrict__ score,
                               float* __restrict__ attn_out) {
    const int n = blockIdx.x;
    const int s = threadIdx.x;  // 128
    float v = score[s * BATCH + n];
    __shared__ float rmax[4], rsum[4];
    float m = warp_max(v);
    if ((s & 31) == 0) rmax[s >> 5] = m;
    __syncthreads();
    m = fmaxf(fmaxf(rmax[0], rmax[1]), fmaxf(rmax[2], rmax[3]));
    float e = expf(v - m);
    float t = warp_sum(e);
    if ((s & 31) == 0) rsum[s >> 5] = t;
    __syncthreads();
    float sum = rsum[0] + rsum[1] + rsum[2] + rsum[3];
    attn_out[s * BATCH + n] = e / sum;
}

// ---------------- context ----------------
__global__ void context_kernel(const float* __restrict__ enc,
                               const float* __restrict__ attn,
                               float* __restrict__ ctx) {
    const int n = blockIdx.x;
    const int tid = threadIdx.x;  // 256
    __shared__ float a[SDIM];
    if (tid < SDIM) a[tid] = attn[tid * BATCH + n];
    __syncthreads();
    float4 acc = make_float4(0.f, 0.f, 0.f, 0.f);
    for (int s = 0; s < SDIM; s++) {
        float4 e = ((const float4*)(enc + ((size_t)s * BATCH + n) * HDIM))[tid];
        float w = a[s];
        acc.x = fmaf(w, e.x, acc.x);
        acc.y = fmaf(w, e.y, acc.y);
        acc.z = fmaf(w, e.z, acc.z);
        acc.w = fmaf(w, e.w, acc.w);
    }
    ((float4*)(ctx + (size_t)n * HDIM))[tid] = acc;
}

// ---------------- GRU combine + LayerNorm ----------------
__global__ void fuse_hln_kernel(const float* __restrict__ gates,
                                const float* __restrict__ t1,
                                const float* __restrict__ t2,
                                const float* __restrict__ hid,
                                const float* __restrict__ lng,
                                const float* __restrict__ lnb,
                                float* __restrict__ hout) {
    const int n = blockIdx.x;
    const int tid = threadIdx.x;  // 256
    float4 z = ((const float4*)(gates + (size_t)n * 2 * HDIM))[tid];
    float4 r = ((const float4*)(gates + (size_t)n * 2 * HDIM + HDIM))[tid];
    float4 a = ((const float4*)(t1 + (size_t)n * HDIM))[tid];
    float4 b = ((const float4*)(t2 + (size_t)n * HDIM))[tid];
    float4 hv = ((const float4*)(hid + (size_t)n * HDIM))[tid];
    float4 hr;
    hr.x = (1.0f - z.x) * hv.x + z.x * tanhf(a.x + r.x * b.x);
    hr.y = (1.0f - z.y) * hv.y + z.y * tanhf(a.y + r.y * b.y);
    hr.z = (1.0f - z.z) * hv.z + z.z * tanhf(a.z + r.z * b.z);
    hr.w = (1.0f - z.w) * hv.w + z.w * tanhf(a.w + r.w * b.w);
    float s = hr.x + hr.y + hr.z + hr.w;
    float ss = hr.x * hr.x + hr.y * hr.y + hr.z * hr.z + hr.w * hr.w;
    __shared__ float sm1[8], sm2[8];
    float w1 = warp_sum(s), w2 = warp_sum(ss);
    if ((tid & 31) == 0) { sm1[tid >> 5] = w1; sm2[tid >> 5] = w2; }
    __syncthreads();
    float tot1 = 0.f, tot2 = 0.f;
#pragma unroll
    for (int qq = 0; qq < 8; qq++) { tot1 += sm1[qq]; tot2 += sm2[qq]; }
    float mu = tot1 * (1.0f / HDIM);
    float var = tot2 * (1.0f / HDIM) - mu * mu;
    float inv = rsqrtf(var + 1e-5f);
    float4 gg = ((const float4*)lng)[tid];
    float4 bb = ((const float4*)lnb)[tid];
    float4 o;
    o.x = (hr.x - mu) * inv * gg.x + bb.x;
    o.y = (hr.y - mu) * inv * gg.y + bb.y;
    o.z = (hr.z - mu) * inv * gg.z + bb.z;
    o.w = (hr.w - mu) * inv * gg.w + bb.w;
    ((float4*)(hout + (size_t)n * HDIM))[tid] = o;
}

// ---------------- log_softmax in place ----------------
__global__ void logsoftmax_kernel(float* __restrict__ logits) {
    const int n = blockIdx.x;
    const int tid = threadIdx.x;  // 512
    float* row = logits + (size_t)n * VDIM;
    __shared__ float sm[16];
    float m = -3.4e38f;
    for (int i = tid; i < VDIM; i += 512) m = fmaxf(m, row[i]);
    m = warp_max(m);
    if ((tid & 31) == 0) sm[tid >> 5] = m;
    __syncthreads();
    float mx = -3.4e38f;
#pragma unroll
    for (int qq = 0; qq < 16; qq++) mx = fmaxf(mx, sm[qq]);
    __syncthreads();
    float s = 0.0f;
    for (int i = tid; i < VDIM; i += 512) s += expf(row[i] - mx);
    s = warp_sum(s);
    if ((tid & 31) == 0) sm[tid >> 5] = s;
    __syncthreads();
    float tot = 0.0f;
#pragma unroll
    for (int qq = 0; qq < 16; qq++) tot += sm[qq];
    float lse = mx + logf(tot);
    for (int i = tid; i < VDIM; i += 512) row[i] = row[i] - lse;
}

// ---------------- launch ----------------
extern "C" void kernel_launch(void* const* d_in, const int* in_sizes, int n_in,
                              void* d_out, int out_size) {
    const int* ids = (const int*)d_in[0];
    const float* hidden = (const float*)d_in[1];
    const float* enc = (const float*)d_in[2];
    const float* emb = (const float*)d_in[3];
    const float* W_w = (const float*)d_in[4];
    const float* W_b = (const float*)d_in[5];
    const float* U_w = (const float*)d_in[6];
    const float* U_b = (const float*)d_in[7];
    const float* v_w = (const float*)d_in[8];
    // d_in[9] = v_b : constant over S, cancels in softmax
    const float* ih_w = (const float*)d_in[10];
    const float* ih_b = (const float*)d_in[11];
    const float* hh_w = (const float*)d_in[12];
    const float* hh_b = (const float*)d_in[13];
    const float* cand_w = (const float*)d_in[14];
    const float* cand_b = (const float*)d_in[15];
    const float* hhc_w = (const float*)d_in[16];
    const float* hhc_b = (const float*)d_in[17];
    const float* comb_w = (const float*)d_in[18];
    const float* comb_b = (const float*)d_in[19];
    const float* ln_g = (const float*)d_in[20];
    const float* ln_b = (const float*)d_in[21];
    const float* out1_w = (const float*)d_in[22];
    const float* out1_b = (const float*)d_in[23];
    const float* out2_w = (const float*)d_in[24];
    const float* out2_b = (const float*)d_in[25];

    float* out_logits = (float*)d_out;
    float* out_h = out_logits + (size_t)BATCH * VDIM;
    float* out_attn = out_h + (size_t)BATCH * HDIM;

    float *Wh, *score, *ctx, *gbuf, *gates, *t1, *t2, *o1;
    cudaGetSymbolAddress((void**)&Wh, g_Wh);
    cudaGetSymbolAddress((void**)&score, g_score);
    cudaGetSymbolAddress((void**)&ctx, g_ctx);
    cudaGetSymbolAddress((void**)&gbuf, g_g);
    cudaGetSymbolAddress((void**)&gates, g_gates);
    cudaGetSymbolAddress((void**)&t1, g_t1);
    cudaGetSymbolAddress((void**)&t2, g_t2);
    cudaGetSymbolAddress((void**)&o1, g_o1);

    // 1. Wh = hidden @ W_w + W_b
    {
        ProbPlain p{hidden, W_w, W_b, Wh, HDIM, HDIM, 0};
        tgemm<ProbPlain><<<dim3(HDIM / 128, BATCH / 128), 256>>>(p);
    }
    // 2. zero score
    zero_kernel<<<(SDIM * BATCH + 255) / 256, 256>>>(score, SDIM * BATCH);
    // 3. fused score GEMM
    {
        ProbScore p{enc, U_w, Wh, U_b, v_w, score, HDIM};
        tgemm<ProbScore><<<dim3(HDIM / 128, (SDIM * BATCH) / 128), 256>>>(p);
    }
    // 4. softmax -> attn output
    softmax_kernel<<<BATCH, SDIM>>>(score, out_attn);
    // 5. context
    context_kernel<<<BATCH, 256>>>(enc, out_attn, ctx);
    // 6. g = relu([emb[ids], ctx] @ comb_w + comb_b)
    {
        ProbComb p{emb, ids, ctx, comb_w, comb_b, gbuf, EDIM + HDIM};
        tgemm<ProbComb><<<dim3(EDIM / 128, BATCH / 128), 256>>>(p);
    }
    // 7. fused gates | t1 | t2
    {
        ProbFused3 p{gbuf, hidden, ih_w, hh_w, cand_w, hhc_w,
                     ih_b, hh_b, cand_b, hhc_b, gates, t1, t2, EDIM + HDIM};
        tgemm<ProbFused3><<<dim3(4096 / 128, BATCH / 128), 256>>>(p);
    }
    // 8. GRU combine + LayerNorm
    fuse_hln_kernel<<<BATCH, 256>>>(gates, t1, t2, hidden, ln_g, ln_b, out_h);
    // 9. o1 = relu(h @ out1_w + out1_b)
    {
        ProbPlain p{out_h, out1_w, out1_b, o1, HDIM, HDIM, 1};
        tgemm<ProbPlain><<<dim3(HDIM / 128, BATCH / 128), 256>>>(p);
    }
    // 10. logits
    {
        ProbOut2 p{o1, out2_w, out2_b, out_logits, HDIM, VDIM};
        tgemm<ProbOut2><<<dim3((VDIM + 127) / 128, BATCH / 128), 256>>>(p);
    }
    // 11. log_softmax
    logsoftmax_kernel<<<BATCH, 512>>>(out_logits);
}

// round 5
// speedup vs baseline: 4.0828x; 1.0677x over previous
#include <cuda_runtime.h>
#include <cstdint>

#define BATCH 256
#define HDIM  1024
#define EDIM  512
#define SDIM  128
#define VDIM  50257

// ---------------- scratch (no allocations allowed) ----------------
__device__ float g_Wh[BATCH * HDIM];
__device__ float g_score[SDIM * BATCH];
__device__ float g_ctx[BATCH * HDIM];
__device__ float g_g[BATCH * EDIM];
__device__ float g_gates[BATCH * 2 * HDIM];
__device__ float g_t1[BATCH * HDIM];
__device__ float g_t2[BATCH * HDIM];
__device__ float g_o1[BATCH * HDIM];

// ---------------- helpers ----------------
__device__ __forceinline__ float warp_sum(float v) {
#pragma unroll
    for (int o = 16; o > 0; o >>= 1) v += __shfl_xor_sync(0xffffffffu, v, o);
    return v;
}
__device__ __forceinline__ float warp_max(float v) {
#pragma unroll
    for (int o = 16; o > 0; o >>= 1) v = fmaxf(v, __shfl_xor_sync(0xffffffffu, v, o));
    return v;
}

__device__ __forceinline__ void mma8(float* c, const uint32_t* a, const uint32_t* b) {
    asm volatile(
        "mma.sync.aligned.m16n8k8.row.col.f32.tf32.tf32.f32 "
        "{%0,%1,%2,%3}, {%4,%5,%6,%7}, {%8,%9}, {%0,%1,%2,%3};"
        : "+f"(c[0]), "+f"(c[1]), "+f"(c[2]), "+f"(c[3])
        : "r"(a[0]), "r"(a[1]), "r"(a[2]), "r"(a[3]), "r"(b[0]), "r"(b[1]));
}

__device__ __forceinline__ void cpa16(void* smem_dst, const void* gsrc) {
    uint32_t d = (uint32_t)__cvta_generic_to_shared(smem_dst);
    asm volatile("cp.async.ca.shared.global [%0], [%1], 16;" ::"r"(d), "l"(gsrc));
}
__device__ __forceinline__ void cpa16z(void* smem_dst, const void* gsrc, int srcsz) {
    uint32_t d = (uint32_t)__cvta_generic_to_shared(smem_dst);
    asm volatile("cp.async.ca.shared.global [%0], [%1], 16, %2;" ::"r"(d), "l"(gsrc),
                 "r"(srcsz));
}
__device__ __forceinline__ void cpa4z(void* smem_dst, const void* gsrc, int srcsz) {
    uint32_t d = (uint32_t)__cvta_generic_to_shared(smem_dst);
    asm volatile("cp.async.ca.shared.global [%0], [%1], 4, %2;" ::"r"(d), "l"(gsrc),
                 "r"(srcsz));
}
__device__ __forceinline__ void cpa_commit() {
    asm volatile("cp.async.commit_group;");
}
__device__ __forceinline__ void cpa_wait1() {
    asm volatile("cp.async.wait_group 1;");
}

__global__ void zero_kernel(float* p, int n) {
    int i = blockIdx.x * blockDim.x + threadIdx.x;
    if (i < n) p[i] = 0.0f;
}

// =====================================================================
// tgemm: 128x128 tile, K-tile 16, double-buffered cp.async (round-3,
// proven). Used for all small GEMMs and out2.
// =====================================================================
template <class P>
__launch_bounds__(256)
__global__ void tgemm(P p) {
    __shared__ float As[2][128][20];
    __shared__ float Bs[2][16][136];

    const int tid = threadIdx.x;
    const int lane = tid & 31, wid = tid >> 5;
    const int wm = wid >> 2, wn = wid & 3;
    const int q = lane >> 2, t = lane & 3;
    const int m0 = blockIdx.y * 128;
    const int n0 = blockIdx.x * 128;

    float acc[4][4][4];
#pragma unroll
    for (int i = 0; i < 4; i++)
#pragma unroll
        for (int j = 0; j < 4; j++)
#pragma unroll
            for (int r = 0; r < 4; r++) acc[i][j][r] = 0.0f;

    auto copyA = [&](int st, int k0) {
#pragma unroll
        for (int i = 0; i < 2; i++) {
            int c = tid + i * 256;
            int row = c >> 2, kp = (c & 3) << 2;
            cpa16(&As[st][row][kp], p.aChunk(m0 + row, k0 + kp));
        }
    };

    const int KT = p.K >> 4;
    copyA(0, 0);
    p.copyB(&Bs[0][0][0], n0, 0, tid);
    cpa_commit();
    copyA(1, 16);
    p.copyB(&Bs[1][0][0], n0, 16, tid);
    cpa_commit();

    for (int kt = 0; kt < KT; kt++) {
        cpa_wait1();
        __syncthreads();
        const int st = kt & 1;

#pragma unroll
        for (int k8 = 0; k8 < 16; k8 += 8) {
            uint32_t af[4][4], bf[4][2];
#pragma unroll
            for (int ni = 0; ni < 4; ni++) {
                int nc = wn * 32 + ni * 8 + q;
                bf[ni][0] = __float_as_uint(Bs[st][k8 + t][nc]);
                bf[ni][1] = __float_as_uint(Bs[st][k8 + t + 4][nc]);
            }
#pragma unroll
            for (int mi = 0; mi < 4; mi++) {
                int mr = wm * 64 + mi * 16 + q;
                af[mi][0] = __float_as_uint(As[st][mr][k8 + t]);
                af[mi][1] = __float_as_uint(As[st][mr + 8][k8 + t]);
                af[mi][2] = __float_as_uint(As[st][mr][k8 + t + 4]);
                af[mi][3] = __float_as_uint(As[st][mr + 8][k8 + t + 4]);
            }
#pragma unroll
            for (int mi = 0; mi < 4; mi++)
#pragma unroll
                for (int ni = 0; ni < 4; ni++) mma8(acc[mi][ni], af[mi], bf[ni]);
        }
        __syncthreads();
        if (kt + 2 < KT) {
            copyA(st, (kt + 2) * 16);
            p.copyB(&Bs[st][0][0], n0, (kt + 2) * 16, tid);
        }
        cpa_commit();
    }
    p.store(acc, m0, n0, tid);
}

__device__ __forceinline__ void copyB_dense(float* bs, const float* B, int ldb, int n0,
                                            int k0, int tid) {
#pragma unroll
    for (int i = 0; i < 2; i++) {
        int c = tid + i * 256;
        int k = c >> 5, np = (c & 31) << 2;
        cpa16(bs + k * 136 + np, B + (size_t)(k0 + k) * ldb + n0 + np);
    }
}

// =====================================================================
// tgemm256: 128x256 tile, 8 warps (64x64 each), K-tile 32,
// double-buffered cp.async, dynamic smem. Used by the score GEMM.
//   As: [2][128][36]  (stride 36 -> frag banks (4q+t), conflict-free)
//   Bs: [2][32][264]  (stride 264 -> frag banks (8t+q), conflict-free)
// =====================================================================
#define A256_ST (128 * 36)
#define B256_ST (32 * 264)
#define SMEM256 ((2 * A256_ST + 2 * B256_ST) * 4)

template <class P>
__launch_bounds__(256)
__global__ void tgemm256(P p) {
    extern __shared__ float dsm[];
    float* Asm = dsm;                  // [2][128][36]
    float* Bsm = dsm + 2 * A256_ST;    // [2][32][264]

    const int tid = threadIdx.x;
    const int lane = tid & 31, wid = tid >> 5;
    const int wm = wid >> 2, wn = wid & 3;
    const int q = lane >> 2, t = lane & 3;
    const int m0 = blockIdx.y * 128;
    const int n0 = blockIdx.x * 256;

    float acc[4][8][4];
#pragma unroll
    for (int i = 0; i < 4; i++)
#pragma unroll
        for (int j = 0; j < 8; j++)
#pragma unroll
            for (int r = 0; r < 4; r++) acc[i][j][r] = 0.0f;

    auto copyA = [&](int st, int k0) {
        float* ab = Asm + st * A256_ST;
#pragma unroll
        for (int i = 0; i < 4; i++) {
            int idx = tid + i * 256;  // 1024 chunks: 128 rows x 8
            int row = idx >> 3, kp = (idx & 7) << 2;
            cpa16(ab + row * 36 + kp, p.aChunk(m0 + row, k0 + kp));
        }
    };

    const int KT = p.K >> 5;
    copyA(0, 0);
    p.copyB(Bsm, n0, 0, tid);
    cpa_commit();
    copyA(1, 32);
    p.copyB(Bsm + B256_ST, n0, 32, tid);
    cpa_commit();

    for (int kt = 0; kt < KT; kt++) {
        cpa_wait1();
        __syncthreads();
        const int st = kt & 1;
        const float* ab = Asm + st * A256_ST;
        const float* bb = Bsm + st * B256_ST;

#pragma unroll
        for (int k8 = 0; k8 < 32; k8 += 8) {
            uint32_t af[4][4], bf[8][2];
#pragma unroll
            for (int ni = 0; ni < 8; ni++) {
                int nc = wn * 64 + ni * 8 + q;
                bf[ni][0] = __float_as_uint(bb[(k8 + t) * 264 + nc]);
                bf[ni][1] = __float_as_uint(bb[(k8 + t + 4) * 264 + nc]);
            }
#pragma unroll
            for (int mi = 0; mi < 4; mi++) {
                int mr = wm * 64 + mi * 16 + q;
                af[mi][0] = __float_as_uint(ab[mr * 36 + k8 + t]);
                af[mi][1] = __float_as_uint(ab[(mr + 8) * 36 + k8 + t]);
                af[mi][2] = __float_as_uint(ab[mr * 36 + k8 + t + 4]);
                af[mi][3] = __float_as_uint(ab[(mr + 8) * 36 + k8 + t + 4]);
            }
#pragma unroll
            for (int mi = 0; mi < 4; mi++)
#pragma unroll
                for (int ni = 0; ni < 8; ni++) mma8(acc[mi][ni], af[mi], bf[ni]);
        }
        __syncthreads();
        if (kt + 2 < KT) {
            copyA(st, (kt + 2) * 32);
            p.copyB(Bsm + st * B256_ST, n0, (kt + 2) * 32, tid);
        }
        cpa_commit();
    }
    p.store(acc, m0, n0, tid, dsm);
}

// ---------------- functors (128-tile) ----------------
struct ProbPlain {
    const float* A;
    const float* B;
    const float* bias;
    float* C;
    int K;
    int N;
    int act;  // 0=none, 1=relu
    __device__ __forceinline__ const float* aChunk(int r, int k) const {
        return A + (size_t)r * K + k;
    }
    __device__ __forceinline__ void copyB(float* bs, int n0, int k0, int tid) const {
        copyB_dense(bs, B, N, n0, k0, tid);
    }
    __device__ __forceinline__ void store(const float (&acc)[4][4][4], int m0, int n0,
                                          int tid) const {
        const int lane = tid & 31, wid = tid >> 5, wm = wid >> 2, wn = wid & 3;
#pragma unroll
        for (int mi = 0; mi < 4; mi++) {
            int r = m0 + wm * 64 + mi * 16 + (lane >> 2);
#pragma unroll
            for (int ni = 0; ni < 4; ni++) {
                int c = n0 + wn * 32 + ni * 8 + (lane & 3) * 2;
                float bx = bias[c], by = bias[c + 1];
                float2 lo = make_float2(acc[mi][ni][0] + bx, acc[mi][ni][1] + by);
                float2 hi = make_float2(acc[mi][ni][2] + bx, acc[mi][ni][3] + by);
                if (act == 1) {
                    lo.x = fmaxf(lo.x, 0.f);
                    lo.y = fmaxf(lo.y, 0.f);
                    hi.x = fmaxf(hi.x, 0.f);
                    hi.y = fmaxf(hi.y, 0.f);
                }
                *(float2*)(C + (size_t)r * N + c) = lo;
                *(float2*)(C + (size_t)(r + 8) * N + c) = hi;
            }
        }
    }
};

struct ProbComb {
    const float* emb;
    const int* ids;
    const float* ctx;
    const float* B;
    const float* bias;
    float* C;
    int K;
    __device__ __forceinline__ const float* aChunk(int r, int k) const {
        if (k < EDIM) return emb + (size_t)__ldg(&ids[r]) * EDIM + k;
        return ctx + (size_t)r * HDIM + (k - EDIM);
    }
    __device__ __forceinline__ void copyB(float* bs, int n0, int k0, int tid) const {
        copyB_dense(bs, B, EDIM, n0, k0, tid);
    }
    __device__ __forceinline__ void store(const float (&acc)[4][4][4], int m0, int n0,
                                          int tid) const {
        const int lane = tid & 31, wid = tid >> 5, wm = wid >> 2, wn = wid & 3;
        const int N = EDIM;
#pragma unroll
        for (int mi = 0; mi < 4; mi++) {
            int r = m0 + wm * 64 + mi * 16 + (lane >> 2);
#pragma unroll
            for (int ni = 0; ni < 4; ni++) {
                int c = n0 + wn * 32 + ni * 8 + (lane & 3) * 2;
                float bx = bias[c], by = bias[c + 1];
                float2 lo = make_float2(fmaxf(acc[mi][ni][0] + bx, 0.f),
                                        fmaxf(acc[mi][ni][1] + by, 0.f));
                float2 hi = make_float2(fmaxf(acc[mi][ni][2] + bx, 0.f),
                                        fmaxf(acc[mi][ni][3] + by, 0.f));
                *(float2*)(C + (size_t)r * N + c) = lo;
                *(float2*)(C + (size_t)(r + 8) * N + c) = hi;
            }
        }
    }
};

struct ProbFused3 {
    const float* g;
    const float* hid;
    const float* ihw;
    const float* hhw;
    const float* candw;
    const float* hhcw;
    const float* ihb;
    const float* hhb;
    const float* candb;
    const float* hhcb;
    float* Cg;
    float* Ct1;
    float* Ct2;
    int K;
    __device__ __forceinline__ const float* aChunk(int r, int k) const {
        if (k < EDIM) return g + (size_t)r * EDIM + k;
        return hid + (size_t)r * HDIM + (k - EDIM);
    }
    __device__ __forceinline__ void copyB(float* bs, int n0, int k0, int tid) const {
#pragma unroll
        for (int i = 0; i < 2; i++) {
            int c = tid + i * 256;
            int k = c >> 5, np = (c & 31) << 2;
            int gk = k0 + k, gc = n0 + np;
            const float* src = ihw;
            int sz = 16;
            if (gc < 2048) {
                src = (gk < EDIM) ? ihw + (size_t)gk * 2048 + gc
                                  : hhw + (size_t)(gk - EDIM) * 2048 + gc;
            } else if (gc < 3072) {
                if (gk < EDIM) src = candw + (size_t)gk * HDIM + (gc - 2048);
                else sz = 0;
            } else {
                if (gk >= EDIM) src = hhcw + (size_t)(gk - EDIM) * HDIM + (gc - 3072);
                else sz = 0;
            }
            cpa16z(bs + k * 136 + np, src, sz);
        }
    }
    __device__ __forceinline__ void store(const float (&acc)[4][4][4], int m0, int n0,
                                          int tid) const {
        const int lane = tid & 31, wid = tid >> 5, wm = wid >> 2, wn = wid & 3;
        float* C;
        const float* b0p;
        const float* b1p;
        int N, cbase, sig;
        if (n0 < 2048) {
            C = Cg; N = 2048; cbase = n0; b0p = ihb; b1p = hhb; sig = 1;
        } else if (n0 < 3072) {
            C = Ct1; N = HDIM; cbase = n0 - 2048; b0p = candb; b1p = nullptr; sig = 0;
        } else {
            C = Ct2; N = HDIM; cbase = n0 - 3072; b0p = hhcb; b1p = nullptr; sig = 0;
        }
#pragma unroll
        for (int mi = 0; mi < 4; mi++) {
            int r = m0 + wm * 64 + mi * 16 + (lane >> 2);
#pragma unroll
            for (int ni = 0; ni < 4; ni++) {
                int c = cbase + wn * 32 + ni * 8 + (lane & 3) * 2;
                float bx = b0p[c], by = b0p[c + 1];
                if (b1p) { bx += b1p[c]; by += b1p[c + 1]; }
                float2 lo = make_float2(acc[mi][ni][0] + bx, acc[mi][ni][1] + by);
                float2 hi = make_float2(acc[mi][ni][2] + bx, acc[mi][ni][3] + by);
                if (sig) {
                    lo.x = 1.f / (1.f + expf(-lo.x));
                    lo.y = 1.f / (1.f + expf(-lo.y));
                    hi.x = 1.f / (1.f + expf(-hi.x));
                    hi.y = 1.f / (1.f + expf(-hi.y));
                }
                *(float2*)(C + (size_t)r * N + c) = lo;
                *(float2*)(C + (size_t)(r + 8) * N + c) = hi;
            }
        }
    }
};

struct ProbOut2 {
    const float* A;
    const float* B;
    const float* bias;
    float* C;
    int K;
    int N;
    __device__ __forceinline__ const float* aChunk(int r, int k) const {
        return A + (size_t)r * K + k;
    }
    __device__ __forceinline__ void copyB(float* bs, int n0, int k0, int tid) const {
#pragma unroll
        for (int i = 0; i < 8; i++) {
            int e = tid + i * 256;
            int k = e >> 7, n = e & 127;
            int gn = n0 + n;
            int ok = gn < N;
            const float* src = B + (size_t)(k0 + k) * N + (ok ? gn : 0);
            cpa4z(bs + k * 136 + n, src, ok ? 4 : 0);
        }
    }
    __device__ __forceinline__ void store(const float (&acc)[4][4][4], int m0, int n0,
                                          int tid) const {
        const int lane = tid & 31, wid = tid >> 5, wm = wid >> 2, wn = wid & 3;
#pragma unroll
        for (int mi = 0; mi < 4; mi++) {
            int r = m0 + wm * 64 + mi * 16 + (lane >> 2);
#pragma unroll
            for (int ni = 0; ni < 4; ni++) {
                int c = n0 + wn * 32 + ni * 8 + (lane & 3) * 2;
#pragma unroll
                for (int rr = 0; rr < 4; rr++) {
                    int cc = c + (rr & 1);
                    int rrr = r + (rr >> 1) * 8;
                    if (cc < N) C[(size_t)rrr * N + cc] = acc[mi][ni][rr] + bias[cc];
                }
            }
        }
    }
};

// ---------------- score functor (256-tile) ----------------
// score[m] += sum_{c in 256-col block} tanh(enc@Uw[m,c] + Wh[m&255,c] + Ub[c]) * vw[c]
struct ProbScore256 {
    const float* enc;  // (S*N, H) row-major
    const float* Uw;   // (H, H) k-major
    const float* Wh;
    const float* Ub;
    const float* vw;
    float* score;
    int K;
    __device__ __forceinline__ const float* aChunk(int r, int k) const {
        return enc + (size_t)r * HDIM + k;
    }
    __device__ __forceinline__ void copyB(float* bs, int n0, int k0, int tid) const {
#pragma unroll
        for (int i = 0; i < 8; i++) {
            int idx = tid + i * 256;  // 2048 chunks: 32 k-rows x 64
            int k = idx >> 6, np = (idx & 63) << 2;
            cpa16(bs + k * 264 + np, Uw + (size_t)(k0 + k) * HDIM + n0 + np);
        }
    }
    __device__ __forceinline__ void store(const float (&acc)[4][8][4], int m0, int n0,
                                          int tid, float* smem) const {
        float* red = smem;  // 4*128 floats, reuses A region (safe post-loop)
        const int lane = tid & 31, wid = tid >> 5, wm = wid >> 2, wn = wid & 3;
        const int q = lane >> 2, t = lane & 3;
        __syncthreads();
#pragma unroll
        for (int mi = 0; mi < 4; mi++) {
            int r0 = m0 + wm * 64 + mi * 16 + q;
            const float* wh0 = Wh + (size_t)(r0 & (BATCH - 1)) * HDIM;
            const float* wh1 = Wh + (size_t)((r0 + 8) & (BATCH - 1)) * HDIM;
            float s0 = 0.f, s1 = 0.f;
#pragma unroll
            for (int ni = 0; ni < 8; ni++) {
                int c = n0 + wn * 64 + ni * 8 + t * 2;
                float u0 = Ub[c], u1 = Ub[c + 1];
                float w0 = vw[c], w1 = vw[c + 1];
                s0 += tanhf(acc[mi][ni][0] + wh0[c] + u0) * w0;
                s0 += tanhf(acc[mi][ni][1] + wh0[c + 1] + u1) * w1;
                s1 += tanhf(acc[mi][ni][2] + wh1[c] + u0) * w0;
                s1 += tanhf(acc[mi][ni][3] + wh1[c + 1] + u1) * w1;
            }
            s0 += __shfl_xor_sync(0xffffffffu, s0, 1);
            s0 += __shfl_xor_sync(0xffffffffu, s0, 2);
            s1 += __shfl_xor_sync(0xffffffffu, s1, 1);
            s1 += __shfl_xor_sync(0xffffffffu, s1, 2);
            if (t == 0) {
                red[wn * 128 + wm * 64 + mi * 16 + q] = s0;
                red[wn * 128 + wm * 64 + mi * 16 + q + 8] = s1;
            }
        }
        __syncthreads();
        if (tid < 128)
            atomicAdd(&score[m0 + tid], red[tid] + red[128 + tid] + red[256 + tid] +
                                            red[384 + tid]);
    }
};

// ---------------- softmax over S (axis 0) -> attn ----------------
__global__ void softmax_kernel(const float* __restrict__ score,
                               float* __restrict__ attn_out) {
    const int n = blockIdx.x;
    const int s = threadIdx.x;  // 128
    float v = score[s * BATCH + n];
    __shared__ float rmax[4], rsum[4];
    float m = warp_max(v);
    if ((s & 31) == 0) rmax[s >> 5] = m;
    __syncthreads();
    m = fmaxf(fmaxf(rmax[0], rmax[1]), fmaxf(rmax[2], rmax[3]));
    float e = expf(v - m);
    float t = warp_sum(e);
    if ((s & 31) == 0) rsum[s >> 5] = t;
    __syncthreads();
    float sum = rsum[0] + rsum[1] + rsum[2] + rsum[3];
    attn_out[s * BATCH + n] = e / sum;
}

// ---------------- context ----------------
__global__ void context_kernel(const float* __restrict__ enc,
                               const float* __restrict__ attn,
                               float* __restrict__ ctx) {
    const int n = blockIdx.x;
    const int tid = threadIdx.x;  // 256
    __shared__ float a[SDIM];
    if (tid < SDIM) a[tid] = attn[tid * BATCH + n];
    __syncthreads();
    float4 acc = make_float4(0.f, 0.f, 0.f, 0.f);
    for (int s = 0; s < SDIM; s++) {
        float4 e = ((const float4*)(enc + ((size_t)s * BATCH + n) * HDIM))[tid];
        float w = a[s];
        acc.x = fmaf(w, e.x, acc.x);
        acc.y = fmaf(w, e.y, acc.y);
        acc.z = fmaf(w, e.z, acc.z);
        acc.w = fmaf(w, e.w, acc.w);
    }
    ((float4*)(ctx + (size_t)n * HDIM))[tid] = acc;
}

// ---------------- GRU combine + LayerNorm ----------------
__global__ void fuse_hln_kernel(const float* __restrict__ gates,
                                const float* __restrict__ t1,
                                const float* __restrict__ t2,
                                const float* __restrict__ hid,
                                const float* __restrict__ lng,
                                const float* __restrict__ lnb,
                                float* __restrict__ hout) {
    const int n = blockIdx.x;
    const int tid = threadIdx.x;  // 256
    float4 z = ((const float4*)(gates + (size_t)n * 2 * HDIM))[tid];
    float4 r = ((const float4*)(gates + (size_t)n * 2 * HDIM + HDIM))[tid];
    float4 a = ((const float4*)(t1 + (size_t)n * HDIM))[tid];
    float4 b = ((const float4*)(t2 + (size_t)n * HDIM))[tid];
    float4 hv = ((const float4*)(hid + (size_t)n * HDIM))[tid];
    float4 hr;
    hr.x = (1.0f - z.x) * hv.x + z.x * tanhf(a.x + r.x * b.x);
    hr.y = (1.0f - z.y) * hv.y + z.y * tanhf(a.y + r.y * b.y);
    hr.z = (1.0f - z.z) * hv.z + z.z * tanhf(a.z + r.z * b.z);
    hr.w = (1.0f - z.w) * hv.w + z.w * tanhf(a.w + r.w * b.w);
    float s = hr.x + hr.y + hr.z + hr.w;
    float ss = hr.x * hr.x + hr.y * hr.y + hr.z * hr.z + hr.w * hr.w;
    __shared__ float sm1[8], sm2[8];
    float w1 = warp_sum(s), w2 = warp_sum(ss);
    if ((tid & 31) == 0) { sm1[tid >> 5] = w1; sm2[tid >> 5] = w2; }
    __syncthreads();
    float tot1 = 0.f, tot2 = 0.f;
#pragma unroll
    for (int qq = 0; qq < 8; qq++) { tot1 += sm1[qq]; tot2 += sm2[qq]; }
    float mu = tot1 * (1.0f / HDIM);
    float var = tot2 * (1.0f / HDIM) - mu * mu;
    float inv = rsqrtf(var + 1e-5f);
    float4 gg = ((const float4*)lng)[tid];
    float4 bb = ((const float4*)lnb)[tid];
    float4 o;
    o.x = (hr.x - mu) * inv * gg.x + bb.x;
    o.y = (hr.y - mu) * inv * gg.y + bb.y;
    o.z = (hr.z - mu) * inv * gg.z + bb.z;
    o.w = (hr.w - mu) * inv * gg.w + bb.w;
    ((float4*)(hout + (size_t)n * HDIM))[tid] = o;
}

// ---------------- log_softmax in place ----------------
__global__ void logsoftmax_kernel(float* __restrict__ logits) {
    const int n = blockIdx.x;
    const int tid = threadIdx.x;  // 512
    float* row = logits + (size_t)n * VDIM;
    __shared__ float sm[16];
    float m = -3.4e38f;
    for (int i = tid; i < VDIM; i += 512) m = fmaxf(m, row[i]);
    m = warp_max(m);
    if ((tid & 31) == 0) sm[tid >> 5] = m;
    __syncthreads();
    float mx = -3.4e38f;
#pragma unroll
    for (int qq = 0; qq < 16; qq++) mx = fmaxf(mx, sm[qq]);
    __syncthreads();
    float s = 0.0f;
    for (int i = tid; i < VDIM; i += 512) s += expf(row[i] - mx);
    s = warp_sum(s);
    if ((tid & 31) == 0) sm[tid >> 5] = s;
    __syncthreads();
    float tot = 0.0f;
#pragma unroll
    for (int qq = 0; qq < 16; qq++) tot += sm[qq];
    float lse = mx + logf(tot);
    for (int i = tid; i < VDIM; i += 512) row[i] = row[i] - lse;
}

// ---------------- launch ----------------
extern "C" void kernel_launch(void* const* d_in, const int* in_sizes, int n_in,
                              void* d_out, int out_size) {
    const int* ids = (const int*)d_in[0];
    const float* hidden = (const float*)d_in[1];
    const float* enc = (const float*)d_in[2];
    const float* emb = (const float*)d_in[3];
    const float* W_w = (const float*)d_in[4];
    const float* W_b = (const float*)d_in[5];
    const float* U_w = (const float*)d_in[6];
    const float* U_b = (const float*)d_in[7];
    const float* v_w = (const float*)d_in[8];
    // d_in[9] = v_b : constant over S, cancels in softmax
    const float* ih_w = (const float*)d_in[10];
    const float* ih_b = (const float*)d_in[11];
    const float* hh_w = (const float*)d_in[12];
    const float* hh_b = (const float*)d_in[13];
    const float* cand_w = (const float*)d_in[14];
    const float* cand_b = (const float*)d_in[15];
    const float* hhc_w = (const float*)d_in[16];
    const float* hhc_b = (const float*)d_in[17];
    const float* comb_w = (const float*)d_in[18];
    const float* comb_b = (const float*)d_in[19];
    const float* ln_g = (const float*)d_in[20];
    const float* ln_b = (const float*)d_in[21];
    const float* out1_w = (const float*)d_in[22];
    const float* out1_b = (const float*)d_in[23];
    const float* out2_w = (const float*)d_in[24];
    const float* out2_b = (const float*)d_in[25];

    float* out_logits = (float*)d_out;
    float* out_h = out_logits + (size_t)BATCH * VDIM;
    float* out_attn = out_h + (size_t)BATCH * HDIM;

    float *Wh, *score, *ctx, *gbuf, *gates, *t1, *t2, *o1;
    cudaGetSymbolAddress((void**)&Wh, g_Wh);
    cudaGetSymbolAddress((void**)&score, g_score);
    cudaGetSymbolAddress((void**)&ctx, g_ctx);
    cudaGetSymbolAddress((void**)&gbuf, g_g);
    cudaGetSymbolAddress((void**)&gates, g_gates);
    cudaGetSymbolAddress((void**)&t1, g_t1);
    cudaGetSymbolAddress((void**)&t2, g_t2);
    cudaGetSymbolAddress((void**)&o1, g_o1);

    cudaFuncSetAttribute(tgemm256<ProbScore256>,
                         cudaFuncAttributeMaxDynamicSharedMemorySize, SMEM256);

    // 1. Wh = hidden @ W_w + W_b
    {
        ProbPlain p{hidden, W_w, W_b, Wh, HDIM, HDIM, 0};
        tgemm<ProbPlain><<<dim3(HDIM / 128, BATCH / 128), 256>>>(p);
    }
    // 2. zero score
    zero_kernel<<<(SDIM * BATCH + 255) / 256, 256>>>(score, SDIM * BATCH);
    // 3. fused score GEMM (128x256 tile, K-tile 32)
    {
        ProbScore256 p{enc, U_w, Wh, U_b, v_w, score, HDIM};
        tgemm256<ProbScore256><<<dim3(HDIM / 256, (SDIM * BATCH) / 128), 256,
                                 SMEM256>>>(p);
    }
    // 4. softmax -> attn output
    softmax_kernel<<<BATCH, SDIM>>>(score, out_attn);
    // 5. context
    context_kernel<<<BATCH, 256>>>(enc, out_attn, ctx);
    // 6. g = relu([emb[ids], ctx] @ comb_w + comb_b)
    {
        ProbComb p{emb, ids, ctx, comb_w, comb_b, gbuf, EDIM + HDIM};
        tgemm<ProbComb><<<dim3(EDIM / 128, BATCH / 128), 256>>>(p);
    }
    // 7. fused gates | t1 | t2
    {
        ProbFused3 p{gbuf, hidden, ih_w, hh_w, cand_w, hhc_w,
                     ih_b, hh_b, cand_b, hhc_b, gates, t1, t2, EDIM + HDIM};
        tgemm<ProbFused3><<<dim3(4096 / 128, BATCH / 128), 256>>>(p);
    }
    // 8. GRU combine + LayerNorm
    fuse_hln_kernel<<<BATCH, 256>>>(gates, t1, t2, hidden, ln_g, ln_b, out_h);
    // 9. o1 = relu(h @ out1_w + out1_b)
    {
        ProbPlain p{out_h, out1_w, out1_b, o1, HDIM, HDIM, 1};
        tgemm<ProbPlain><<<dim3(HDIM / 128, BATCH / 128), 256>>>(p);
    }
    // 10. logits
    {
        ProbOut2 p{o1, out2_w, out2_b, out_logits, HDIM, VDIM};
        tgemm<ProbOut2><<<dim3((VDIM + 127) / 128, BATCH / 128), 256>>>(p);
    }
    // 11. log_softmax
    logsoftmax_kernel<<<BATCH, 512>>>(out_logits);
}

// round 7
// speedup vs baseline: 4.8230x; 1.1813x over previous
#include <cuda_runtime.h>
#include <cuda_fp16.h>
#include <cstdint>

#define BATCH 256
#define HDIM  1024
#define EDIM  512
#define SDIM  128
#define VDIM  50257
#define VPAD  50432  // VDIM padded to multiple of 256 (16B-aligned cp.async rows)

// ---------------- scratch (no allocations allowed) ----------------
__device__ float g_Wh[BATCH * HDIM];
__device__ float g_score[SDIM * BATCH];
__device__ float g_ctx[BATCH * HDIM];
__device__ float g_g[BATCH * EDIM];
__device__ float g_gates[BATCH * 2 * HDIM];
__device__ float g_t1[BATCH * HDIM];
__device__ float g_t2[BATCH * HDIM];
__device__ float g_o1[BATCH * HDIM];
__device__ __half g_encH[SDIM * BATCH * HDIM];   // enc as fp16
__device__ __half g_o1h[BATCH * HDIM];           // o1 as fp16
__device__ uint32_t g_UwP[(HDIM / 2) * HDIM];    // U_w k-pair packed
__device__ uint32_t g_out2P[(HDIM / 2) * VPAD];  // out2_w k-pair packed, padded rows

// ---------------- helpers ----------------
__device__ __forceinline__ float warp_sum(float v) {
#pragma unroll
    for (int o = 16; o > 0; o >>= 1) v += __shfl_xor_sync(0xffffffffu, v, o);
    return v;
}
__device__ __forceinline__ float warp_max(float v) {
#pragma unroll
    for (int o = 16; o > 0; o >>= 1) v = fmaxf(v, __shfl_xor_sync(0xffffffffu, v, o));
    return v;
}

__device__ __forceinline__ void mma8(float* c, const uint32_t* a, const uint32_t* b) {
    asm volatile(
        "mma.sync.aligned.m16n8k8.row.col.f32.tf32.tf32.f32 "
        "{%0,%1,%2,%3}, {%4,%5,%6,%7}, {%8,%9}, {%0,%1,%2,%3};"
        : "+f"(c[0]), "+f"(c[1]), "+f"(c[2]), "+f"(c[3])
        : "r"(a[0]), "r"(a[1]), "r"(a[2]), "r"(a[3]), "r"(b[0]), "r"(b[1]));
}
__device__ __forceinline__ void mma16(float* c, const uint32_t* a, const uint32_t* b) {
    asm volatile(
        "mma.sync.aligned.m16n8k16.row.col.f32.f16.f16.f32 "
        "{%0,%1,%2,%3}, {%4,%5,%6,%7}, {%8,%9}, {%0,%1,%2,%3};"
        : "+f"(c[0]), "+f"(c[1]), "+f"(c[2]), "+f"(c[3])
        : "r"(a[0]), "r"(a[1]), "r"(a[2]), "r"(a[3]), "r"(b[0]), "r"(b[1]));
}

__device__ __forceinline__ void cpa16(void* smem_dst, const void* gsrc) {
    uint32_t d = (uint32_t)__cvta_generic_to_shared(smem_dst);
    asm volatile("cp.async.ca.shared.global [%0], [%1], 16;" ::"r"(d), "l"(gsrc));
}
__device__ __forceinline__ void cpa16z(void* smem_dst, const void* gsrc, int srcsz) {
    uint32_t d = (uint32_t)__cvta_generic_to_shared(smem_dst);
    asm volatile("cp.async.ca.shared.global [%0], [%1], 16, %2;" ::"r"(d), "l"(gsrc),
                 "r"(srcsz));
}
__device__ __forceinline__ void cpa_commit() {
    asm volatile("cp.async.commit_group;");
}
__device__ __forceinline__ void cpa_wait1() {
    asm volatile("cp.async.wait_group 1;");
}

__global__ void zero_kernel(float* p, int n) {
    int i = blockIdx.x * blockDim.x + threadIdx.x;
    if (i < n) p[i] = 0.0f;
}

// fp32 -> fp16, n multiple of 4
__global__ void f2h_kernel(const float* __restrict__ src, __half* __restrict__ dst,
                           int n) {
    int i = (blockIdx.x * blockDim.x + threadIdx.x) * 4;
    if (i < n) {
        float4 v = *(const float4*)(src + i);
        __half2 h0 = __floats2half2_rn(v.x, v.y);
        __half2 h1 = __floats2half2_rn(v.z, v.w);
        *(__half2*)(dst + i) = h0;
        *(__half2*)(dst + i + 2) = h1;
    }
}

// pack B[k][n] fp32 (row stride N) -> BP[k/2][n] u32 (row stride NP, zero-padded)
__global__ void packb_kernel(const float* __restrict__ B, uint32_t* __restrict__ BP,
                             int N, int NP) {
    int n = blockIdx.x * blockDim.x + threadIdx.x;
    int k2 = blockIdx.y;
    if (n < NP) {
        uint32_t out = 0;
        if (n < N) {
            __half2 h = __floats2half2_rn(B[(size_t)(2 * k2) * N + n],
                                          B[(size_t)(2 * k2 + 1) * N + n]);
            out = *(uint32_t*)&h;
        }
        BP[(size_t)k2 * NP + n] = out;
    }
}

// =====================================================================
// tgemm: tf32, 128x128 tile, K-tile 16 (proven). Small GEMMs.
// =====================================================================
template <class P>
__launch_bounds__(256)
__global__ void tgemm(P p) {
    __shared__ float As[2][128][20];
    __shared__ float Bs[2][16][136];

    const int tid = threadIdx.x;
    const int lane = tid & 31, wid = tid >> 5;
    const int wm = wid >> 2, wn = wid & 3;
    const int q = lane >> 2, t = lane & 3;
    const int m0 = blockIdx.y * 128;
    const int n0 = blockIdx.x * 128;

    float acc[4][4][4];
#pragma unroll
    for (int i = 0; i < 4; i++)
#pragma unroll
        for (int j = 0; j < 4; j++)
#pragma unroll
            for (int r = 0; r < 4; r++) acc[i][j][r] = 0.0f;

    auto copyA = [&](int st, int k0) {
#pragma unroll
        for (int i = 0; i < 2; i++) {
            int c = tid + i * 256;
            int row = c >> 2, kp = (c & 3) << 2;
            cpa16(&As[st][row][kp], p.aChunk(m0 + row, k0 + kp));
        }
    };

    const int KT = p.K >> 4;
    copyA(0, 0);
    p.copyB(&Bs[0][0][0], n0, 0, tid);
    cpa_commit();
    copyA(1, 16);
    p.copyB(&Bs[1][0][0], n0, 16, tid);
    cpa_commit();

    for (int kt = 0; kt < KT; kt++) {
        cpa_wait1();
        __syncthreads();
        const int st = kt & 1;

#pragma unroll
        for (int k8 = 0; k8 < 16; k8 += 8) {
            uint32_t af[4][4], bf[4][2];
#pragma unroll
            for (int ni = 0; ni < 4; ni++) {
                int nc = wn * 32 + ni * 8 + q;
                bf[ni][0] = __float_as_uint(Bs[st][k8 + t][nc]);
                bf[ni][1] = __float_as_uint(Bs[st][k8 + t + 4][nc]);
            }
#pragma unroll
            for (int mi = 0; mi < 4; mi++) {
                int mr = wm * 64 + mi * 16 + q;
                af[mi][0] = __float_as_uint(As[st][mr][k8 + t]);
                af[mi][1] = __float_as_uint(As[st][mr + 8][k8 + t]);
                af[mi][2] = __float_as_uint(As[st][mr][k8 + t + 4]);
                af[mi][3] = __float_as_uint(As[st][mr + 8][k8 + t + 4]);
            }
#pragma unroll
            for (int mi = 0; mi < 4; mi++)
#pragma unroll
                for (int ni = 0; ni < 4; ni++) mma8(acc[mi][ni], af[mi], bf[ni]);
        }
        __syncthreads();
        if (kt + 2 < KT) {
            copyA(st, (kt + 2) * 16);
            p.copyB(&Bs[st][0][0], n0, (kt + 2) * 16, tid);
        }
        cpa_commit();
    }
    p.store(acc, m0, n0, tid);
}

__device__ __forceinline__ void copyB_dense(float* bs, const float* B, int ldb, int n0,
                                            int k0, int tid) {
#pragma unroll
    for (int i = 0; i < 2; i++) {
        int c = tid + i * 256;
        int k = c >> 5, np = (c & 31) << 2;
        cpa16(bs + k * 136 + np, B + (size_t)(k0 + k) * ldb + n0 + np);
    }
}

// =====================================================================
// tgemm256h: fp16, 128x256 tile, 8 warps (64x64), K-tile 32 (2 x k16),
// double-buffered cp.async, dynamic smem (~54KB).
//   Asm: u32[2][128][20] (row = 16 u32 = 32 fp16, pad 20)
//   Bsm: u32[2][16][264] (16 k-pair rows, pad 264)
// =====================================================================
#define AH_ST (128 * 20)
#define BH_ST (16 * 264)
#define SMEMH ((2 * AH_ST + 2 * BH_ST) * 4)

template <class P>
__launch_bounds__(256)
__global__ void tgemm256h(P p) {
    extern __shared__ uint32_t dsm[];
    uint32_t* Asm = dsm;              // [2][128][20]
    uint32_t* Bsm = dsm + 2 * AH_ST;  // [2][16][264]

    const int tid = threadIdx.x;
    const int lane = tid & 31, wid = tid >> 5;
    const int wm = wid >> 2, wn = wid & 3;
    const int q = lane >> 2, t = lane & 3;
    const int m0 = blockIdx.y * 128;
    const int n0 = blockIdx.x * 256;

    float acc[4][8][4];
#pragma unroll
    for (int i = 0; i < 4; i++)
#pragma unroll
        for (int j = 0; j < 8; j++)
#pragma unroll
            for (int r = 0; r < 4; r++) acc[i][j][r] = 0.0f;

    auto copyA = [&](int st, int k0) {
        uint32_t* ab = Asm + st * AH_ST;
#pragma unroll
        for (int i = 0; i < 2; i++) {
            int idx = tid + i * 256;  // 512 chunks: 128 rows x 4 (8 fp16 each)
            int row = idx >> 2, c8 = (idx & 3);
            cpa16(ab + row * 20 + c8 * 4, p.aChunkH(m0 + row, k0 + c8 * 8));
        }
    };

    const int KT = p.K >> 5;
    copyA(0, 0);
    p.copyBP(Bsm, n0, 0, tid);
    cpa_commit();
    copyA(1, 32);
    p.copyBP(Bsm + BH_ST, n0, 32, tid);
    cpa_commit();

    for (int kt = 0; kt < KT; kt++) {
        cpa_wait1();
        __syncthreads();
        const int st = kt & 1;
        const uint32_t* ab = Asm + st * AH_ST;
        const uint32_t* bb = Bsm + st * BH_ST;

#pragma unroll
        for (int g = 0; g < 2; g++) {  // two k16 groups
            const int o = g * 8;
            uint32_t af[4][4], bf[8][2];
#pragma unroll
            for (int ni = 0; ni < 8; ni++) {
                int nc = wn * 64 + ni * 8 + q;
                bf[ni][0] = bb[(o + t) * 264 + nc];
                bf[ni][1] = bb[(o + t + 4) * 264 + nc];
            }
#pragma unroll
            for (int mi = 0; mi < 4; mi++) {
                int mr = wm * 64 + mi * 16 + q;
                af[mi][0] = ab[mr * 20 + o + t];
                af[mi][1] = ab[(mr + 8) * 20 + o + t];
                af[mi][2] = ab[mr * 20 + o + t + 4];
                af[mi][3] = ab[(mr + 8) * 20 + o + t + 4];
            }
#pragma unroll
            for (int mi = 0; mi < 4; mi++)
#pragma unroll
                for (int ni = 0; ni < 8; ni++) mma16(acc[mi][ni], af[mi], bf[ni]);
        }
        __syncthreads();
        if (kt + 2 < KT) {
            copyA(st, (kt + 2) * 32);
            p.copyBP(Bsm + st * BH_ST, n0, (kt + 2) * 32, tid);
        }
        cpa_commit();
    }
    p.store(acc, m0, n0, tid, (float*)dsm);
}

// ---------------- fp16 functors ----------------
// score[m] += sum_c tanh(enc@Uw[m,c] + Wh[m&255,c] + Ub[c]) * vw[c]
struct ScoreH {
    const __half* encH;   // (S*N, H)
    const uint32_t* UwP;  // packed [H/2][H]
    const float* Wh;
    const float* Ub;
    const float* vw;
    float* score;
    int K;
    __device__ __forceinline__ const __half* aChunkH(int r, int k) const {
        return encH + (size_t)r * HDIM + k;
    }
    __device__ __forceinline__ void copyBP(uint32_t* bs, int n0, int k0,
                                           int tid) const {
        const int k20 = k0 >> 1;
#pragma unroll
        for (int i = 0; i < 4; i++) {
            int idx = tid + i * 256;  // 1024 chunks: 16 k2-rows x 64 (4 u32 each)
            int k2 = idx >> 6, np = (idx & 63) << 2;
            cpa16(bs + k2 * 264 + np, UwP + (size_t)(k20 + k2) * HDIM + n0 + np);
        }
    }
    __device__ __forceinline__ void store(const float (&acc)[4][8][4], int m0, int n0,
                                          int tid, float* smem) const {
        float* red = smem;  // 4*128 floats, safe post-loop
        const int lane = tid & 31, wid = tid >> 5, wm = wid >> 2, wn = wid & 3;
        const int q = lane >> 2, t = lane & 3;
        __syncthreads();
#pragma unroll
        for (int mi = 0; mi < 4; mi++) {
            int r0 = m0 + wm * 64 + mi * 16 + q;
            const float* wh0 = Wh + (size_t)(r0 & (BATCH - 1)) * HDIM;
            const float* wh1 = Wh + (size_t)((r0 + 8) & (BATCH - 1)) * HDIM;
            float s0 = 0.f, s1 = 0.f;
#pragma unroll
            for (int ni = 0; ni < 8; ni++) {
                int c = n0 + wn * 64 + ni * 8 + t * 2;
                float u0 = Ub[c], u1 = Ub[c + 1];
                float w0 = vw[c], w1 = vw[c + 1];
                s0 += tanhf(acc[mi][ni][0] + wh0[c] + u0) * w0;
                s0 += tanhf(acc[mi][ni][1] + wh0[c + 1] + u1) * w1;
                s1 += tanhf(acc[mi][ni][2] + wh1[c] + u0) * w0;
                s1 += tanhf(acc[mi][ni][3] + wh1[c + 1] + u1) * w1;
            }
            s0 += __shfl_xor_sync(0xffffffffu, s0, 1);
            s0 += __shfl_xor_sync(0xffffffffu, s0, 2);
            s1 += __shfl_xor_sync(0xffffffffu, s1, 1);
            s1 += __shfl_xor_sync(0xffffffffu, s1, 2);
            if (t == 0) {
                red[wn * 128 + wm * 64 + mi * 16 + q] = s0;
                red[wn * 128 + wm * 64 + mi * 16 + q + 8] = s1;
            }
        }
        __syncthreads();
        if (tid < 128)
            atomicAdd(&score[m0 + tid],
                      red[tid] + red[128 + tid] + red[256 + tid] + red[384 + tid]);
    }
};

// logits = o1h @ out2P + out2_b ; B rows padded to VPAD (16B-aligned chunks)
struct Out2H {
    const __half* AH;     // o1 fp16 (256, 1024)
    const uint32_t* BP;   // packed [512][VPAD]
    const float* bias;
    float* C;
    int K;
    int N;
    __device__ __forceinline__ const __half* aChunkH(int r, int k) const {
        return AH + (size_t)r * HDIM + k;
    }
    __device__ __forceinline__ void copyBP(uint32_t* bs, int n0, int k0,
                                           int tid) const {
        const int k20 = k0 >> 1;
#pragma unroll
        for (int i = 0; i < 4; i++) {
            int idx = tid + i * 256;
            int k2 = idx >> 6, np = (idx & 63) << 2;
            // n0+np < VPAD always (n0 <= 50176, np <= 252); rows zero-padded
            cpa16(bs + k2 * 264 + np, BP + (size_t)(k20 + k2) * VPAD + n0 + np);
        }
    }
    __device__ __forceinline__ void store(const float (&acc)[4][8][4], int m0, int n0,
                                          int tid, float* smem) const {
        const int lane = tid & 31, wid = tid >> 5, wm = wid >> 2, wn = wid & 3;
#pragma unroll
        for (int mi = 0; mi < 4; mi++) {
            int r = m0 + wm * 64 + mi * 16 + (lane >> 2);
#pragma unroll
            for (int ni = 0; ni < 8; ni++) {
                int c = n0 + wn * 64 + ni * 8 + (lane & 3) * 2;
#pragma unroll
                for (int rr = 0; rr < 4; rr++) {
                    int cc = c + (rr & 1);
                    int rrr = r + (rr >> 1) * 8;
                    if (cc < N) C[(size_t)rrr * N + cc] = acc[mi][ni][rr] + bias[cc];
                }
            }
        }
    }
};

// ---------------- tf32 functors (small GEMMs) ----------------
struct ProbPlain {
    const float* A;
    const float* B;
    const float* bias;
    float* C;
    int K;
    int N;
    int act;  // 0=none, 1=relu
    __device__ __forceinline__ const float* aChunk(int r, int k) const {
        return A + (size_t)r * K + k;
    }
    __device__ __forceinline__ void copyB(float* bs, int n0, int k0, int tid) const {
        copyB_dense(bs, B, N, n0, k0, tid);
    }
    __device__ __forceinline__ void store(const float (&acc)[4][4][4], int m0, int n0,
                                          int tid) const {
        const int lane = tid & 31, wid = tid >> 5, wm = wid >> 2, wn = wid & 3;
#pragma unroll
        for (int mi = 0; mi < 4; mi++) {
            int r = m0 + wm * 64 + mi * 16 + (lane >> 2);
#pragma unroll
            for (int ni = 0; ni < 4; ni++) {
                int c = n0 + wn * 32 + ni * 8 + (lane & 3) * 2;
                float bx = bias[c], by = bias[c + 1];
                float2 lo = make_float2(acc[mi][ni][0] + bx, acc[mi][ni][1] + by);
                float2 hi = make_float2(acc[mi][ni][2] + bx, acc[mi][ni][3] + by);
                if (act == 1) {
                    lo.x = fmaxf(lo.x, 0.f);
                    lo.y = fmaxf(lo.y, 0.f);
                    hi.x = fmaxf(hi.x, 0.f);
                    hi.y = fmaxf(hi.y, 0.f);
                }
                *(float2*)(C + (size_t)r * N + c) = lo;
                *(float2*)(C + (size_t)(r + 8) * N + c) = hi;
            }
        }
    }
};

struct ProbComb {
    const float* emb;
    const int* ids;
    const float* ctx;
    const float* B;
    const float* bias;
    float* C;
    int K;
    __device__ __forceinline__ const float* aChunk(int r, int k) const {
        if (k < EDIM) return emb + (size_t)__ldg(&ids[r]) * EDIM + k;
        return ctx + (size_t)r * HDIM + (k - EDIM);
    }
    __device__ __forceinline__ void copyB(float* bs, int n0, int k0, int tid) const {
        copyB_dense(bs, B, EDIM, n0, k0, tid);
    }
    __device__ __forceinline__ void store(const float (&acc)[4][4][4], int m0, int n0,
                                          int tid) const {
        const int lane = tid & 31, wid = tid >> 5, wm = wid >> 2, wn = wid & 3;
        const int N = EDIM;
#pragma unroll
        for (int mi = 0; mi < 4; mi++) {
            int r = m0 + wm * 64 + mi * 16 + (lane >> 2);
#pragma unroll
            for (int ni = 0; ni < 4; ni++) {
                int c = n0 + wn * 32 + ni * 8 + (lane & 3) * 2;
                float bx = bias[c], by = bias[c + 1];
                float2 lo = make_float2(fmaxf(acc[mi][ni][0] + bx, 0.f),
                                        fmaxf(acc[mi][ni][1] + by, 0.f));
                float2 hi = make_float2(fmaxf(acc[mi][ni][2] + bx, 0.f),
                                        fmaxf(acc[mi][ni][3] + by, 0.f));
                *(float2*)(C + (size_t)r * N + c) = lo;
                *(float2*)(C + (size_t)(r + 8) * N + c) = hi;
            }
        }
    }
};

struct ProbFused3 {
    const float* g;
    const float* hid;
    const float* ihw;
    const float* hhw;
    const float* candw;
    const float* hhcw;
    const float* ihb;
    const float* hhb;
    const float* candb;
    const float* hhcb;
    float* Cg;
    float* Ct1;
    float* Ct2;
    int K;
    __device__ __forceinline__ const float* aChunk(int r, int k) const {
        if (k < EDIM) return g + (size_t)r * EDIM + k;
        return hid + (size_t)r * HDIM + (k - EDIM);
    }
    __device__ __forceinline__ void copyB(float* bs, int n0, int k0, int tid) const {
#pragma unroll
        for (int i = 0; i < 2; i++) {
            int c = tid + i * 256;
            int k = c >> 5, np = (c & 31) << 2;
            int gk = k0 + k, gc = n0 + np;
            const float* src = ihw;
            int sz = 16;
            if (gc < 2048) {
                src = (gk < EDIM) ? ihw + (size_t)gk * 2048 + gc
                                  : hhw + (size_t)(gk - EDIM) * 2048 + gc;
            } else if (gc < 3072) {
                if (gk < EDIM) src = candw + (size_t)gk * HDIM + (gc - 2048);
                else sz = 0;
            } else {
                if (gk >= EDIM) src = hhcw + (size_t)(gk - EDIM) * HDIM + (gc - 3072);
                else sz = 0;
            }
            cpa16z(bs + k * 136 + np, src, sz);
        }
    }
    __device__ __forceinline__ void store(const float (&acc)[4][4][4], int m0, int n0,
                                          int tid) const {
        const int lane = tid & 31, wid = tid >> 5, wm = wid >> 2, wn = wid & 3;
        float* C;
        const float* b0p;
        const float* b1p;
        int N, cbase, sig;
        if (n0 < 2048) {
            C = Cg; N = 2048; cbase = n0; b0p = ihb; b1p = hhb; sig = 1;
        } else if (n0 < 3072) {
            C = Ct1; N = HDIM; cbase = n0 - 2048; b0p = candb; b1p = nullptr; sig = 0;
        } else {
            C = Ct2; N = HDIM; cbase = n0 - 3072; b0p = hhcb; b1p = nullptr; sig = 0;
        }
#pragma unroll
        for (int mi = 0; mi < 4; mi++) {
            int r = m0 + wm * 64 + mi * 16 + (lane >> 2);
#pragma unroll
            for (int ni = 0; ni < 4; ni++) {
                int c = cbase + wn * 32 + ni * 8 + (lane & 3) * 2;
                float bx = b0p[c], by = b0p[c + 1];
                if (b1p) { bx += b1p[c]; by += b1p[c + 1]; }
                float2 lo = make_float2(acc[mi][ni][0] + bx, acc[mi][ni][1] + by);
                float2 hi = make_float2(acc[mi][ni][2] + bx, acc[mi][ni][3] + by);
                if (sig) {
                    lo.x = 1.f / (1.f + expf(-lo.x));
                    lo.y = 1.f / (1.f + expf(-lo.y));
                    hi.x = 1.f / (1.f + expf(-hi.x));
                    hi.y = 1.f / (1.f + expf(-hi.y));
                }
                *(float2*)(C + (size_t)r * N + c) = lo;
                *(float2*)(C + (size_t)(r + 8) * N + c) = hi;
            }
        }
    }
};

// ---------------- softmax over S (axis 0) -> attn ----------------
__global__ void softmax_kernel(const float* __restrict__ score,
                               float* __restrict__ attn_out) {
    const int n = blockIdx.x;
    const int s = threadIdx.x;  // 128
    float v = score[s * BATCH + n];
    __shared__ float rmax[4], rsum[4];
    float m = warp_max(v);
    if ((s & 31) == 0) rmax[s >> 5] = m;
    __syncthreads();
    m = fmaxf(fmaxf(rmax[0], rmax[1]), fmaxf(rmax[2], rmax[3]));
    float e = expf(v - m);
    float t = warp_sum(e);
    if ((s & 31) == 0) rsum[s >> 5] = t;
    __syncthreads();
    float sum = rsum[0] + rsum[1] + rsum[2] + rsum[3];
    attn_out[s * BATCH + n] = e / sum;
}

// ---------------- context ----------------
__global__ void context_kernel(const float* __restrict__ enc,
                               const float* __restrict__ attn,
                               float* __restrict__ ctx) {
    const int n = blockIdx.x;
    const int tid = threadIdx.x;  // 256
    __shared__ float a[SDIM];
    if (tid < SDIM) a[tid] = attn[tid * BATCH + n];
    __syncthreads();
    float4 acc = make_float4(0.f, 0.f, 0.f, 0.f);
    for (int s = 0; s < SDIM; s++) {
        float4 e = ((const float4*)(enc + ((size_t)s * BATCH + n) * HDIM))[tid];
        float w = a[s];
        acc.x = fmaf(w, e.x, acc.x);
        acc.y = fmaf(w, e.y, acc.y);
        acc.z = fmaf(w, e.z, acc.z);
        acc.w = fmaf(w, e.w, acc.w);
    }
    ((float4*)(ctx + (size_t)n * HDIM))[tid] = acc;
}

// ---------------- GRU combine + LayerNorm ----------------
__global__ void fuse_hln_kernel(const float* __restrict__ gates,
                                const float* __restrict__ t1,
                                const float* __restrict__ t2,
                                const float* __restrict__ hid,
                                const float* __restrict__ lng,
                                const float* __restrict__ lnb,
                                float* __restrict__ hout) {
    const int n = blockIdx.x;
    const int tid = threadIdx.x;  // 256
    float4 z = ((const float4*)(gates + (size_t)n * 2 * HDIM))[tid];
    float4 r = ((const float4*)(gates + (size_t)n * 2 * HDIM + HDIM))[tid];
    float4 a = ((const float4*)(t1 + (size_t)n * HDIM))[tid];
    float4 b = ((const float4*)(t2 + (size_t)n * HDIM))[tid];
    float4 hv = ((const float4*)(hid + (size_t)n * HDIM))[tid];
    float4 hr;
    hr.x = (1.0f - z.x) * hv.x + z.x * tanhf(a.x + r.x * b.x);
    hr.y = (1.0f - z.y) * hv.y + z.y * tanhf(a.y + r.y * b.y);
    hr.z = (1.0f - z.z) * hv.z + z.z * tanhf(a.z + r.z * b.z);
    hr.w = (1.0f - z.w) * hv.w + z.w * tanhf(a.w + r.w * b.w);
    float s = hr.x + hr.y + hr.z + hr.w;
    float ss = hr.x * hr.x + hr.y * hr.y + hr.z * hr.z + hr.w * hr.w;
    __shared__ float sm1[8], sm2[8];
    float w1 = warp_sum(s), w2 = warp_sum(ss);
    if ((tid & 31) == 0) { sm1[tid >> 5] = w1; sm2[tid >> 5] = w2; }
    __syncthreads();
    float tot1 = 0.f, tot2 = 0.f;
#pragma unroll
    for (int qq = 0; qq < 8; qq++) { tot1 += sm1[qq]; tot2 += sm2[qq]; }
    float mu = tot1 * (1.0f / HDIM);
    float var = tot2 * (1.0f / HDIM) - mu * mu;
    float inv = rsqrtf(var + 1e-5f);
    float4 gg = ((const float4*)lng)[tid];
    float4 bb = ((const float4*)lnb)[tid];
    float4 o;
    o.x = (hr.x - mu) * inv * gg.x + bb.x;
    o.y = (hr.y - mu) * inv * gg.y + bb.y;
    o.z = (hr.z - mu) * inv * gg.z + bb.z;
    o.w = (hr.w - mu) * inv * gg.w + bb.w;
    ((float4*)(hout + (size_t)n * HDIM))[tid] = o;
}

// ---------------- log_softmax in place ----------------
__global__ void logsoftmax_kernel(float* __restrict__ logits) {
    const int n = blockIdx.x;
    const int tid = threadIdx.x;  // 512
    float* row = logits + (size_t)n * VDIM;
    __shared__ float sm[16];
    float m = -3.4e38f;
    for (int i = tid; i < VDIM; i += 512) m = fmaxf(m, row[i]);
    m = warp_max(m);
    if ((tid & 31) == 0) sm[tid >> 5] = m;
    __syncthreads();
    float mx = -3.4e38f;
#pragma unroll
    for (int qq = 0; qq < 16; qq++) mx = fmaxf(mx, sm[qq]);
    __syncthreads();
    float s = 0.0f;
    for (int i = tid; i < VDIM; i += 512) s += expf(row[i] - mx);
    s = warp_sum(s);
    if ((tid & 31) == 0) sm[tid >> 5] = s;
    __syncthreads();
    float tot = 0.0f;
#pragma unroll
    for (int qq = 0; qq < 16; qq++) tot += sm[qq];
    float lse = mx + logf(tot);
    for (int i = tid; i < VDIM; i += 512) row[i] = row[i] - lse;
}

// ---------------- launch ----------------
extern "C" void kernel_launch(void* const* d_in, const int* in_sizes, int n_in,
                              void* d_out, int out_size) {
    const int* ids = (const int*)d_in[0];
    const float* hidden = (const float*)d_in[1];
    const float* enc = (const float*)d_in[2];
    const float* emb = (const float*)d_in[3];
    const float* W_w = (const float*)d_in[4];
    const float* W_b = (const float*)d_in[5];
    const float* U_w = (const float*)d_in[6];
    const float* U_b = (const float*)d_in[7];
    const float* v_w = (const float*)d_in[8];
    // d_in[9] = v_b : constant over S, cancels in softmax
    const float* ih_w = (const float*)d_in[10];
    const float* ih_b = (const float*)d_in[11];
    const float* hh_w = (const float*)d_in[12];
    const float* hh_b = (const float*)d_in[13];
    const float* cand_w = (const float*)d_in[14];
    const float* cand_b = (const float*)d_in[15];
    const float* hhc_w = (const float*)d_in[16];
    const float* hhc_b = (const float*)d_in[17];
    const float* comb_w = (const float*)d_in[18];
    const float* comb_b = (const float*)d_in[19];
    const float* ln_g = (const float*)d_in[20];
    const float* ln_b = (const float*)d_in[21];
    const float* out1_w = (const float*)d_in[22];
    const float* out1_b = (const float*)d_in[23];
    const float* out2_w = (const float*)d_in[24];
    const float* out2_b = (const float*)d_in[25];

    float* out_logits = (float*)d_out;
    float* out_h = out_logits + (size_t)BATCH * VDIM;
    float* out_attn = out_h + (size_t)BATCH * HDIM;

    float *Wh, *score, *ctx, *gbuf, *gates, *t1, *t2, *o1;
    __half *encH, *o1h;
    uint32_t *UwP, *out2P;
    cudaGetSymbolAddress((void**)&Wh, g_Wh);
    cudaGetSymbolAddress((void**)&score, g_score);
    cudaGetSymbolAddress((void**)&ctx, g_ctx);
    cudaGetSymbolAddress((void**)&gbuf, g_g);
    cudaGetSymbolAddress((void**)&gates, g_gates);
    cudaGetSymbolAddress((void**)&t1, g_t1);
    cudaGetSymbolAddress((void**)&t2, g_t2);
    cudaGetSymbolAddress((void**)&o1, g_o1);
    cudaGetSymbolAddress((void**)&encH, g_encH);
    cudaGetSymbolAddress((void**)&o1h, g_o1h);
    cudaGetSymbolAddress((void**)&UwP, g_UwP);
    cudaGetSymbolAddress((void**)&out2P, g_out2P);

    cudaFuncSetAttribute(tgemm256h<ScoreH>,
                         cudaFuncAttributeMaxDynamicSharedMemorySize, SMEMH);
    cudaFuncSetAttribute(tgemm256h<Out2H>,
                         cudaFuncAttributeMaxDynamicSharedMemorySize, SMEMH);

    // 0. conversions
    f2h_kernel<<<(SDIM * BATCH * HDIM) / 1024, 256>>>(enc, encH, SDIM * BATCH * HDIM);
    packb_kernel<<<dim3(HDIM / 256, HDIM / 2), 256>>>(U_w, UwP, HDIM, HDIM);
    packb_kernel<<<dim3(VPAD / 256, HDIM / 2), 256>>>(out2_w, out2P, VDIM, VPAD);

    // 1. Wh = hidden @ W_w + W_b (tf32)
    {
        ProbPlain p{hidden, W_w, W_b, Wh, HDIM, HDIM, 0};
        tgemm<ProbPlain><<<dim3(HDIM / 128, BATCH / 128), 256>>>(p);
    }
    // 2. zero score
    zero_kernel<<<(SDIM * BATCH + 255) / 256, 256>>>(score, SDIM * BATCH);
    // 3. fused score GEMM (fp16 tensor core)
    {
        ScoreH p{encH, UwP, Wh, U_b, v_w, score, HDIM};
        tgemm256h<ScoreH><<<dim3(HDIM / 256, (SDIM * BATCH) / 128), 256, SMEMH>>>(p);
    }
    // 4. softmax -> attn output
    softmax_kernel<<<BATCH, SDIM>>>(score, out_attn);
    // 5. context
    context_kernel<<<BATCH, 256>>>(enc, out_attn, ctx);
    // 6. g = relu([emb[ids], ctx] @ comb_w + comb_b)
    {
        ProbComb p{emb, ids, ctx, comb_w, comb_b, gbuf, EDIM + HDIM};
        tgemm<ProbComb><<<dim3(EDIM / 128, BATCH / 128), 256>>>(p);
    }
    // 7. fused gates | t1 | t2
    {
        ProbFused3 p{gbuf, hidden, ih_w, hh_w, cand_w, hhc_w,
                     ih_b, hh_b, cand_b, hhc_b, gates, t1, t2, EDIM + HDIM};
        tgemm<ProbFused3><<<dim3(4096 / 128, BATCH / 128), 256>>>(p);
    }
    // 8. GRU combine + LayerNorm
    fuse_hln_kernel<<<BATCH, 256>>>(gates, t1, t2, hidden, ln_g, ln_b, out_h);
    // 9. o1 = relu(h @ out1_w + out1_b), then fp16 copy
    {
        ProbPlain p{out_h, out1_w, out1_b, o1, HDIM, HDIM, 1};
        tgemm<ProbPlain><<<dim3(HDIM / 128, BATCH / 128), 256>>>(p);
    }
    f2h_kernel<<<(BATCH * HDIM) / 1024, 256>>>(o1, o1h, BATCH * HDIM);
    // 10. logits = o1h @ out2P + out2_b (fp16 tensor core)
    {
        Out2H p{o1h, out2P, out2_b, out_logits, HDIM, VDIM};
        tgemm256h<Out2H><<<dim3((VDIM + 255) / 256, BATCH / 128), 256, SMEMH>>>(p);
    }
    // 11. log_softmax
    logsoftmax_kernel<<<BATCH, 512>>>(out_logits);
}

// round 8
// speedup vs baseline: 5.6358x; 1.1685x over previous
#include <cuda_runtime.h>
#include <cuda_fp16.h>
#include <cstdint>

#define BATCH 256
#define HDIM  1024
#define EDIM  512
#define SDIM  128
#define VDIM  50257
#define VPAD  50432  // VDIM padded to multiple of 256 (16B-aligned cp.async rows)

// ---------------- scratch (no allocations allowed) ----------------
__device__ float g_Wh[BATCH * HDIM];
__device__ float g_score[SDIM * BATCH];
__device__ float g_ctx[BATCH * HDIM];
__device__ float g_g[BATCH * EDIM];
__device__ float g_gates[BATCH * 2 * HDIM];
__device__ float g_t1[BATCH * HDIM];
__device__ float g_t2[BATCH * HDIM];
__device__ float g_o1[BATCH * HDIM];
__device__ __half g_encH[SDIM * BATCH * HDIM];   // enc as fp16
__device__ __half g_o1h[BATCH * HDIM];           // o1 as fp16
__device__ uint32_t g_UwP[(HDIM / 2) * HDIM];    // U_w k-pair packed
__device__ uint32_t g_out2P[(HDIM / 2) * VPAD];  // out2_w k-pair packed, padded rows

// ---------------- helpers ----------------
__device__ __forceinline__ float warp_sum(float v) {
#pragma unroll
    for (int o = 16; o > 0; o >>= 1) v += __shfl_xor_sync(0xffffffffu, v, o);
    return v;
}
__device__ __forceinline__ float warp_max(float v) {
#pragma unroll
    for (int o = 16; o > 0; o >>= 1) v = fmaxf(v, __shfl_xor_sync(0xffffffffu, v, o));
    return v;
}

__device__ __forceinline__ void mma8(float* c, const uint32_t* a, const uint32_t* b) {
    asm volatile(
        "mma.sync.aligned.m16n8k8.row.col.f32.tf32.tf32.f32 "
        "{%0,%1,%2,%3}, {%4,%5,%6,%7}, {%8,%9}, {%0,%1,%2,%3};"
        : "+f"(c[0]), "+f"(c[1]), "+f"(c[2]), "+f"(c[3])
        : "r"(a[0]), "r"(a[1]), "r"(a[2]), "r"(a[3]), "r"(b[0]), "r"(b[1]));
}
__device__ __forceinline__ void mma16(float* c, const uint32_t* a, const uint32_t* b) {
    asm volatile(
        "mma.sync.aligned.m16n8k16.row.col.f32.f16.f16.f32 "
        "{%0,%1,%2,%3}, {%4,%5,%6,%7}, {%8,%9}, {%0,%1,%2,%3};"
        : "+f"(c[0]), "+f"(c[1]), "+f"(c[2]), "+f"(c[3])
        : "r"(a[0]), "r"(a[1]), "r"(a[2]), "r"(a[3]), "r"(b[0]), "r"(b[1]));
}

__device__ __forceinline__ void cpa16(void* smem_dst, const void* gsrc) {
    uint32_t d = (uint32_t)__cvta_generic_to_shared(smem_dst);
    asm volatile("cp.async.ca.shared.global [%0], [%1], 16;" ::"r"(d), "l"(gsrc));
}
__device__ __forceinline__ void cpa16z(void* smem_dst, const void* gsrc, int srcsz) {
    uint32_t d = (uint32_t)__cvta_generic_to_shared(smem_dst);
    asm volatile("cp.async.ca.shared.global [%0], [%1], 16, %2;" ::"r"(d), "l"(gsrc),
                 "r"(srcsz));
}
__device__ __forceinline__ void cpa_commit() {
    asm volatile("cp.async.commit_group;");
}
__device__ __forceinline__ void cpa_wait1() {
    asm volatile("cp.async.wait_group 1;");
}

__global__ void zero_kernel(float* p, int n) {
    int i = blockIdx.x * blockDim.x + threadIdx.x;
    if (i < n) p[i] = 0.0f;
}

// fp32 -> fp16, n multiple of 4
__global__ void f2h_kernel(const float* __restrict__ src, __half* __restrict__ dst,
                           int n) {
    int i = (blockIdx.x * blockDim.x + threadIdx.x) * 4;
    if (i < n) {
        float4 v = *(const float4*)(src + i);
        __half2 h0 = __floats2half2_rn(v.x, v.y);
        __half2 h1 = __floats2half2_rn(v.z, v.w);
        *(__half2*)(dst + i) = h0;
        *(__half2*)(dst + i + 2) = h1;
    }
}

// pack B[k][n] fp32 (row stride N) -> BP[k/2][n] u32 (row stride NP, zero-padded)
__global__ void packb_kernel(const float* __restrict__ B, uint32_t* __restrict__ BP,
                             int N, int NP) {
    int n = blockIdx.x * blockDim.x + threadIdx.x;
    int k2 = blockIdx.y;
    if (n < NP) {
        uint32_t out = 0;
        if (n < N) {
            __half2 h = __floats2half2_rn(B[(size_t)(2 * k2) * N + n],
                                          B[(size_t)(2 * k2 + 1) * N + n]);
            out = *(uint32_t*)&h;
        }
        BP[(size_t)k2 * NP + n] = out;
    }
}

// =====================================================================
// tgemm64: tf32, 64x64 tile, 128 threads (4 warps of 32x32), K-tile 32,
// double-buffered cp.async. For the small (M=256) GEMMs — 4x more blocks
// than the 128x128 tile -> latency/BW bound fixed.
//   As: [2][64][36]  (frag banks 4q+t, conflict-free)
//   Bs: [2][32][72]  (frag banks 8t+q, conflict-free)
// =====================================================================
template <class P>
__launch_bounds__(128)
__global__ void tgemm64(P p) {
    __shared__ float As[2][64][36];
    __shared__ float Bs[2][32][72];

    const int tid = threadIdx.x;
    const int lane = tid & 31, wid = tid >> 5;
    const int wm = wid >> 1, wn = wid & 1;
    const int q = lane >> 2, t = lane & 3;
    const int m0 = blockIdx.y * 64;
    const int n0 = blockIdx.x * 64;

    float acc[2][4][4];
#pragma unroll
    for (int i = 0; i < 2; i++)
#pragma unroll
        for (int j = 0; j < 4; j++)
#pragma unroll
            for (int r = 0; r < 4; r++) acc[i][j][r] = 0.0f;

    auto copyA = [&](int st, int k0) {
#pragma unroll
        for (int i = 0; i < 4; i++) {
            int c = tid + i * 128;  // 512 chunks: 64 rows x 8
            int row = c >> 3, kp = (c & 7) << 2;
            cpa16(&As[st][row][kp], p.aChunk(m0 + row, k0 + kp));
        }
    };

    const int KT = p.K >> 5;
    copyA(0, 0);
    p.copyB(&Bs[0][0][0], n0, 0, tid);
    cpa_commit();
    copyA(1, 32);
    p.copyB(&Bs[1][0][0], n0, 32, tid);
    cpa_commit();

    for (int kt = 0; kt < KT; kt++) {
        cpa_wait1();
        __syncthreads();
        const int st = kt & 1;

#pragma unroll
        for (int k8 = 0; k8 < 32; k8 += 8) {
            uint32_t af[2][4], bf[4][2];
#pragma unroll
            for (int ni = 0; ni < 4; ni++) {
                int nc = wn * 32 + ni * 8 + q;
                bf[ni][0] = __float_as_uint(Bs[st][k8 + t][nc]);
                bf[ni][1] = __float_as_uint(Bs[st][k8 + t + 4][nc]);
            }
#pragma unroll
            for (int mi = 0; mi < 2; mi++) {
                int mr = wm * 32 + mi * 16 + q;
                af[mi][0] = __float_as_uint(As[st][mr][k8 + t]);
                af[mi][1] = __float_as_uint(As[st][mr + 8][k8 + t]);
                af[mi][2] = __float_as_uint(As[st][mr][k8 + t + 4]);
                af[mi][3] = __float_as_uint(As[st][mr + 8][k8 + t + 4]);
            }
#pragma unroll
            for (int mi = 0; mi < 2; mi++)
#pragma unroll
                for (int ni = 0; ni < 4; ni++) mma8(acc[mi][ni], af[mi], bf[ni]);
        }
        __syncthreads();
        if (kt + 2 < KT) {
            copyA(st, (kt + 2) * 32);
            p.copyB(&Bs[st][0][0], n0, (kt + 2) * 32, tid);
        }
        cpa_commit();
    }
    p.store(acc, m0, n0, tid);
}

// dense 64-wide B copier: 512 x 16B chunks (32 k-rows x 16), row stride ldb
__device__ __forceinline__ void copyB64_dense(float* bs, const float* B, int ldb,
                                              int n0, int k0, int tid) {
#pragma unroll
    for (int i = 0; i < 4; i++) {
        int c = tid + i * 128;
        int k = c >> 4, np = (c & 15) << 2;
        cpa16(bs + k * 72 + np, B + (size_t)(k0 + k) * ldb + n0 + np);
    }
}

// ---------------- tgemm64 functors ----------------
struct Plain64 {
    const float* A;
    const float* B;
    const float* bias;
    float* C;
    int K;
    int N;
    int act;  // 0=none, 1=relu
    __device__ __forceinline__ const float* aChunk(int r, int k) const {
        return A + (size_t)r * K + k;
    }
    __device__ __forceinline__ void copyB(float* bs, int n0, int k0, int tid) const {
        copyB64_dense(bs, B, N, n0, k0, tid);
    }
    __device__ __forceinline__ void store(const float (&acc)[2][4][4], int m0, int n0,
                                          int tid) const {
        const int lane = tid & 31, wid = tid >> 5, wm = wid >> 1, wn = wid & 1;
#pragma unroll
        for (int mi = 0; mi < 2; mi++) {
            int r = m0 + wm * 32 + mi * 16 + (lane >> 2);
#pragma unroll
            for (int ni = 0; ni < 4; ni++) {
                int c = n0 + wn * 32 + ni * 8 + (lane & 3) * 2;
                float bx = bias[c], by = bias[c + 1];
                float2 lo = make_float2(acc[mi][ni][0] + bx, acc[mi][ni][1] + by);
                float2 hi = make_float2(acc[mi][ni][2] + bx, acc[mi][ni][3] + by);
                if (act == 1) {
                    lo.x = fmaxf(lo.x, 0.f);
                    lo.y = fmaxf(lo.y, 0.f);
                    hi.x = fmaxf(hi.x, 0.f);
                    hi.y = fmaxf(hi.y, 0.f);
                }
                *(float2*)(C + (size_t)r * N + c) = lo;
                *(float2*)(C + (size_t)(r + 8) * N + c) = hi;
            }
        }
    }
};

// g = relu([emb[ids], ctx] @ comb_w + comb_b), K=1536, N=512
struct Comb64 {
    const float* emb;
    const int* ids;
    const float* ctx;
    const float* B;
    const float* bias;
    float* C;
    int K;
    __device__ __forceinline__ const float* aChunk(int r, int k) const {
        if (k < EDIM) return emb + (size_t)__ldg(&ids[r]) * EDIM + k;
        return ctx + (size_t)r * HDIM + (k - EDIM);
    }
    __device__ __forceinline__ void copyB(float* bs, int n0, int k0, int tid) const {
        copyB64_dense(bs, B, EDIM, n0, k0, tid);
    }
    __device__ __forceinline__ void store(const float (&acc)[2][4][4], int m0, int n0,
                                          int tid) const {
        const int lane = tid & 31, wid = tid >> 5, wm = wid >> 1, wn = wid & 1;
        const int N = EDIM;
#pragma unroll
        for (int mi = 0; mi < 2; mi++) {
            int r = m0 + wm * 32 + mi * 16 + (lane >> 2);
#pragma unroll
            for (int ni = 0; ni < 4; ni++) {
                int c = n0 + wn * 32 + ni * 8 + (lane & 3) * 2;
                float bx = bias[c], by = bias[c + 1];
                float2 lo = make_float2(fmaxf(acc[mi][ni][0] + bx, 0.f),
                                        fmaxf(acc[mi][ni][1] + by, 0.f));
                float2 hi = make_float2(fmaxf(acc[mi][ni][2] + bx, 0.f),
                                        fmaxf(acc[mi][ni][3] + by, 0.f));
                *(float2*)(C + (size_t)r * N + c) = lo;
                *(float2*)(C + (size_t)(r + 8) * N + c) = hi;
            }
        }
    }
};

// Fused gates|t1|t2. A=[g(512), hidden(1024)] K=1536. Virtual B cols:
// [0,2048): [ih_w;hh_w]->sigmoid->gates; [2048,3072): [cand_w;0]->t1;
// [3072,4096): [0;hhc_w]->t2. 64-tiles never straddle region boundaries.
struct Fused3_64 {
    const float* g;
    const float* hid;
    const float* ihw;
    const float* hhw;
    const float* candw;
    const float* hhcw;
    const float* ihb;
    const float* hhb;
    const float* candb;
    const float* hhcb;
    float* Cg;
    float* Ct1;
    float* Ct2;
    int K;
    __device__ __forceinline__ const float* aChunk(int r, int k) const {
        if (k < EDIM) return g + (size_t)r * EDIM + k;
        return hid + (size_t)r * HDIM + (k - EDIM);
    }
    __device__ __forceinline__ void copyB(float* bs, int n0, int k0, int tid) const {
#pragma unroll
        for (int i = 0; i < 4; i++) {
            int c = tid + i * 128;
            int k = c >> 4, np = (c & 15) << 2;
            int gk = k0 + k, gc = n0 + np;
            const float* src = ihw;  // valid dummy for zfill
            int sz = 16;
            if (gc < 2048) {
                src = (gk < EDIM) ? ihw + (size_t)gk * 2048 + gc
                                  : hhw + (size_t)(gk - EDIM) * 2048 + gc;
            } else if (gc < 3072) {
                if (gk < EDIM) src = candw + (size_t)gk * HDIM + (gc - 2048);
                else sz = 0;
            } else {
                if (gk >= EDIM) src = hhcw + (size_t)(gk - EDIM) * HDIM + (gc - 3072);
                else sz = 0;
            }
            cpa16z(bs + k * 72 + np, src, sz);
        }
    }
    __device__ __forceinline__ void store(const float (&acc)[2][4][4], int m0, int n0,
                                          int tid) const {
        const int lane = tid & 31, wid = tid >> 5, wm = wid >> 1, wn = wid & 1;
        float* C;
        const float* b0p;
        const float* b1p;
        int N, cbase, sig;
        if (n0 < 2048) {
            C = Cg; N = 2048; cbase = n0; b0p = ihb; b1p = hhb; sig = 1;
        } else if (n0 < 3072) {
            C = Ct1; N = HDIM; cbase = n0 - 2048; b0p = candb; b1p = nullptr; sig = 0;
        } else {
            C = Ct2; N = HDIM; cbase = n0 - 3072; b0p = hhcb; b1p = nullptr; sig = 0;
        }
#pragma unroll
        for (int mi = 0; mi < 2; mi++) {
            int r = m0 + wm * 32 + mi * 16 + (lane >> 2);
#pragma unroll
            for (int ni = 0; ni < 4; ni++) {
                int c = cbase + wn * 32 + ni * 8 + (lane & 3) * 2;
                float bx = b0p[c], by = b0p[c + 1];
                if (b1p) { bx += b1p[c]; by += b1p[c + 1]; }
                float2 lo = make_float2(acc[mi][ni][0] + bx, acc[mi][ni][1] + by);
                float2 hi = make_float2(acc[mi][ni][2] + bx, acc[mi][ni][3] + by);
                if (sig) {
                    lo.x = 1.f / (1.f + expf(-lo.x));
                    lo.y = 1.f / (1.f + expf(-lo.y));
                    hi.x = 1.f / (1.f + expf(-hi.x));
                    hi.y = 1.f / (1.f + expf(-hi.y));
                }
                *(float2*)(C + (size_t)r * N + c) = lo;
                *(float2*)(C + (size_t)(r + 8) * N + c) = hi;
            }
        }
    }
};

// =====================================================================
// tgemm256h: fp16, 128x256 tile, 8 warps (64x64), K-tile 32 (2 x k16),
// double-buffered cp.async, dynamic smem (~54KB). Score + out2.
// =====================================================================
#define AH_ST (128 * 20)
#define BH_ST (16 * 264)
#define SMEMH ((2 * AH_ST + 2 * BH_ST) * 4)

template <class P>
__launch_bounds__(256)
__global__ void tgemm256h(P p) {
    extern __shared__ uint32_t dsm[];
    uint32_t* Asm = dsm;              // [2][128][20]
    uint32_t* Bsm = dsm + 2 * AH_ST;  // [2][16][264]

    const int tid = threadIdx.x;
    const int lane = tid & 31, wid = tid >> 5;
    const int wm = wid >> 2, wn = wid & 3;
    const int q = lane >> 2, t = lane & 3;
    const int m0 = blockIdx.y * 128;
    const int n0 = blockIdx.x * 256;

    float acc[4][8][4];
#pragma unroll
    for (int i = 0; i < 4; i++)
#pragma unroll
        for (int j = 0; j < 8; j++)
#pragma unroll
            for (int r = 0; r < 4; r++) acc[i][j][r] = 0.0f;

    auto copyA = [&](int st, int k0) {
        uint32_t* ab = Asm + st * AH_ST;
#pragma unroll
        for (int i = 0; i < 2; i++) {
            int idx = tid + i * 256;  // 512 chunks: 128 rows x 4 (8 fp16 each)
            int row = idx >> 2, c8 = (idx & 3);
            cpa16(ab + row * 20 + c8 * 4, p.aChunkH(m0 + row, k0 + c8 * 8));
        }
    };

    const int KT = p.K >> 5;
    copyA(0, 0);
    p.copyBP(Bsm, n0, 0, tid);
    cpa_commit();
    copyA(1, 32);
    p.copyBP(Bsm + BH_ST, n0, 32, tid);
    cpa_commit();

    for (int kt = 0; kt < KT; kt++) {
        cpa_wait1();
        __syncthreads();
        const int st = kt & 1;
        const uint32_t* ab = Asm + st * AH_ST;
        const uint32_t* bb = Bsm + st * BH_ST;

#pragma unroll
        for (int g = 0; g < 2; g++) {  // two k16 groups
            const int o = g * 8;
            uint32_t af[4][4], bf[8][2];
#pragma unroll
            for (int ni = 0; ni < 8; ni++) {
                int nc = wn * 64 + ni * 8 + q;
                bf[ni][0] = bb[(o + t) * 264 + nc];
                bf[ni][1] = bb[(o + t + 4) * 264 + nc];
            }
#pragma unroll
            for (int mi = 0; mi < 4; mi++) {
                int mr = wm * 64 + mi * 16 + q;
                af[mi][0] = ab[mr * 20 + o + t];
                af[mi][1] = ab[(mr + 8) * 20 + o + t];
                af[mi][2] = ab[mr * 20 + o + t + 4];
                af[mi][3] = ab[(mr + 8) * 20 + o + t + 4];
            }
#pragma unroll
            for (int mi = 0; mi < 4; mi++)
#pragma unroll
                for (int ni = 0; ni < 8; ni++) mma16(acc[mi][ni], af[mi], bf[ni]);
        }
        __syncthreads();
        if (kt + 2 < KT) {
            copyA(st, (kt + 2) * 32);
            p.copyBP(Bsm + st * BH_ST, n0, (kt + 2) * 32, tid);
        }
        cpa_commit();
    }
    p.store(acc, m0, n0, tid, (float*)dsm);
}

// ---------------- fp16 functors ----------------
// score[m] += sum_c tanh(enc@Uw[m,c] + Wh[m&255,c] + Ub[c]) * vw[c]
struct ScoreH {
    const __half* encH;   // (S*N, H)
    const uint32_t* UwP;  // packed [H/2][H]
    const float* Wh;
    const float* Ub;
    const float* vw;
    float* score;
    int K;
    __device__ __forceinline__ const __half* aChunkH(int r, int k) const {
        return encH + (size_t)r * HDIM + k;
    }
    __device__ __forceinline__ void copyBP(uint32_t* bs, int n0, int k0,
                                           int tid) const {
        const int k20 = k0 >> 1;
#pragma unroll
        for (int i = 0; i < 4; i++) {
            int idx = tid + i * 256;  // 1024 chunks: 16 k2-rows x 64 (4 u32 each)
            int k2 = idx >> 6, np = (idx & 63) << 2;
            cpa16(bs + k2 * 264 + np, UwP + (size_t)(k20 + k2) * HDIM + n0 + np);
        }
    }
    __device__ __forceinline__ void store(const float (&acc)[4][8][4], int m0, int n0,
                                          int tid, float* smem) const {
        float* red = smem;  // 4*128 floats, safe post-loop
        const int lane = tid & 31, wid = tid >> 5, wm = wid >> 2, wn = wid & 3;
        const int q = lane >> 2, t = lane & 3;
        __syncthreads();
#pragma unroll
        for (int mi = 0; mi < 4; mi++) {
            int r0 = m0 + wm * 64 + mi * 16 + q;
            const float* wh0 = Wh + (size_t)(r0 & (BATCH - 1)) * HDIM;
            const float* wh1 = Wh + (size_t)((r0 + 8) & (BATCH - 1)) * HDIM;
            float s0 = 0.f, s1 = 0.f;
#pragma unroll
            for (int ni = 0; ni < 8; ni++) {
                int c = n0 + wn * 64 + ni * 8 + t * 2;
                float u0 = Ub[c], u1 = Ub[c + 1];
                float w0 = vw[c], w1 = vw[c + 1];
                s0 += tanhf(acc[mi][ni][0] + wh0[c] + u0) * w0;
                s0 += tanhf(acc[mi][ni][1] + wh0[c + 1] + u1) * w1;
                s1 += tanhf(acc[mi][ni][2] + wh1[c] + u0) * w0;
                s1 += tanhf(acc[mi][ni][3] + wh1[c + 1] + u1) * w1;
            }
            s0 += __shfl_xor_sync(0xffffffffu, s0, 1);
            s0 += __shfl_xor_sync(0xffffffffu, s0, 2);
            s1 += __shfl_xor_sync(0xffffffffu, s1, 1);
            s1 += __shfl_xor_sync(0xffffffffu, s1, 2);
            if (t == 0) {
                red[wn * 128 + wm * 64 + mi * 16 + q] = s0;
                red[wn * 128 + wm * 64 + mi * 16 + q + 8] = s1;
            }
        }
        __syncthreads();
        if (tid < 128)
            atomicAdd(&score[m0 + tid],
                      red[tid] + red[128 + tid] + red[256 + tid] + red[384 + tid]);
    }
};

// logits = o1h @ out2P + out2_b ; B rows padded to VPAD (16B-aligned chunks)
struct Out2H {
    const __half* AH;     // o1 fp16 (256, 1024)
    const uint32_t* BP;   // packed [512][VPAD]
    const float* bias;
    float* C;
    int K;
    int N;
    __device__ __forceinline__ const __half* aChunkH(int r, int k) const {
        return AH + (size_t)r * HDIM + k;
    }
    __device__ __forceinline__ void copyBP(uint32_t* bs, int n0, int k0,
                                           int tid) const {
        const int k20 = k0 >> 1;
#pragma unroll
        for (int i = 0; i < 4; i++) {
            int idx = tid + i * 256;
            int k2 = idx >> 6, np = (idx & 63) << 2;
            cpa16(bs + k2 * 264 + np, BP + (size_t)(k20 + k2) * VPAD + n0 + np);
        }
    }
    __device__ __forceinline__ void store(const float (&acc)[4][8][4], int m0, int n0,
                                          int tid, float* smem) const {
        const int lane = tid & 31, wid = tid >> 5, wm = wid >> 2, wn = wid & 3;
#pragma unroll
        for (int mi = 0; mi < 4; mi++) {
            int r = m0 + wm * 64 + mi * 16 + (lane >> 2);
#pragma unroll
            for (int ni = 0; ni < 8; ni++) {
                int c = n0 + wn * 64 + ni * 8 + (lane & 3) * 2;
#pragma unroll
                for (int rr = 0; rr < 4; rr++) {
                    int cc = c + (rr & 1);
                    int rrr = r + (rr >> 1) * 8;
                    if (cc < N) C[(size_t)rrr * N + cc] = acc[mi][ni][rr] + bias[cc];
                }
            }
        }
    }
};

// ---------------- softmax over S (axis 0) -> attn ----------------
__global__ void softmax_kernel(const float* __restrict__ score,
                               float* __restrict__ attn_out) {
    const int n = blockIdx.x;
    const int s = threadIdx.x;  // 128
    float v = score[s * BATCH + n];
    __shared__ float rmax[4], rsum[4];
    float m = warp_max(v);
    if ((s & 31) == 0) rmax[s >> 5] = m;
    __syncthreads();
    m = fmaxf(fmaxf(rmax[0], rmax[1]), fmaxf(rmax[2], rmax[3]));
    float e = expf(v - m);
    float t = warp_sum(e);
    if ((s & 31) == 0) rsum[s >> 5] = t;
    __syncthreads();
    float sum = rsum[0] + rsum[1] + rsum[2] + rsum[3];
    attn_out[s * BATCH + n] = e / sum;
}

// ---------------- context ----------------
__global__ void context_kernel(const float* __restrict__ enc,
                               const float* __restrict__ attn,
                               float* __restrict__ ctx) {
    const int n = blockIdx.x;
    const int tid = threadIdx.x;  // 256
    __shared__ float a[SDIM];
    if (tid < SDIM) a[tid] = attn[tid * BATCH + n];
    __syncthreads();
    float4 acc = make_float4(0.f, 0.f, 0.f, 0.f);
    for (int s = 0; s < SDIM; s++) {
        float4 e = ((const float4*)(enc + ((size_t)s * BATCH + n) * HDIM))[tid];
        float w = a[s];
        acc.x = fmaf(w, e.x, acc.x);
        acc.y = fmaf(w, e.y, acc.y);
        acc.z = fmaf(w, e.z, acc.z);
        acc.w = fmaf(w, e.w, acc.w);
    }
    ((float4*)(ctx + (size_t)n * HDIM))[tid] = acc;
}

// ---------------- GRU combine + LayerNorm ----------------
__global__ void fuse_hln_kernel(const float* __restrict__ gates,
                                const float* __restrict__ t1,
                                const float* __restrict__ t2,
                                const float* __restrict__ hid,
                                const float* __restrict__ lng,
                                const float* __restrict__ lnb,
                                float* __restrict__ hout) {
    const int n = blockIdx.x;
    const int tid = threadIdx.x;  // 256
    float4 z = ((const float4*)(gates + (size_t)n * 2 * HDIM))[tid];
    float4 r = ((const float4*)(gates + (size_t)n * 2 * HDIM + HDIM))[tid];
    float4 a = ((const float4*)(t1 + (size_t)n * HDIM))[tid];
    float4 b = ((const float4*)(t2 + (size_t)n * HDIM))[tid];
    float4 hv = ((const float4*)(hid + (size_t)n * HDIM))[tid];
    float4 hr;
    hr.x = (1.0f - z.x) * hv.x + z.x * tanhf(a.x + r.x * b.x);
    hr.y = (1.0f - z.y) * hv.y + z.y * tanhf(a.y + r.y * b.y);
    hr.z = (1.0f - z.z) * hv.z + z.z * tanhf(a.z + r.z * b.z);
    hr.w = (1.0f - z.w) * hv.w + z.w * tanhf(a.w + r.w * b.w);
    float s = hr.x + hr.y + hr.z + hr.w;
    float ss = hr.x * hr.x + hr.y * hr.y + hr.z * hr.z + hr.w * hr.w;
    __shared__ float sm1[8], sm2[8];
    float w1 = warp_sum(s), w2 = warp_sum(ss);
    if ((tid & 31) == 0) { sm1[tid >> 5] = w1; sm2[tid >> 5] = w2; }
    __syncthreads();
    float tot1 = 0.f, tot2 = 0.f;
#pragma unroll
    for (int qq = 0; qq < 8; qq++) { tot1 += sm1[qq]; tot2 += sm2[qq]; }
    float mu = tot1 * (1.0f / HDIM);
    float var = tot2 * (1.0f / HDIM) - mu * mu;
    float inv = rsqrtf(var + 1e-5f);
    float4 gg = ((const float4*)lng)[tid];
    float4 bb = ((const float4*)lnb)[tid];
    float4 o;
    o.x = (hr.x - mu) * inv * gg.x + bb.x;
    o.y = (hr.y - mu) * inv * gg.y + bb.y;
    o.z = (hr.z - mu) * inv * gg.z + bb.z;
    o.w = (hr.w - mu) * inv * gg.w + bb.w;
    ((float4*)(hout + (size_t)n * HDIM))[tid] = o;
}

// ---------------- log_softmax in place ----------------
__global__ void logsoftmax_kernel(float* __restrict__ logits) {
    const int n = blockIdx.x;
    const int tid = threadIdx.x;  // 512
    float* row = logits + (size_t)n * VDIM;
    __shared__ float sm[16];
    float m = -3.4e38f;
    for (int i = tid; i < VDIM; i += 512) m = fmaxf(m, row[i]);
    m = warp_max(m);
    if ((tid & 31) == 0) sm[tid >> 5] = m;
    __syncthreads();
    float mx = -3.4e38f;
#pragma unroll
    for (int qq = 0; qq < 16; qq++) mx = fmaxf(mx, sm[qq]);
    __syncthreads();
    float s = 0.0f;
    for (int i = tid; i < VDIM; i += 512) s += expf(row[i] - mx);
    s = warp_sum(s);
    if ((tid & 31) == 0) sm[tid >> 5] = s;
    __syncthreads();
    float tot = 0.0f;
#pragma unroll
    for (int qq = 0; qq < 16; qq++) tot += sm[qq];
    float lse = mx + logf(tot);
    for (int i = tid; i < VDIM; i += 512) row[i] = row[i] - lse;
}

// ---------------- launch ----------------
extern "C" void kernel_launch(void* const* d_in, const int* in_sizes, int n_in,
                              void* d_out, int out_size) {
    const int* ids = (const int*)d_in[0];
    const float* hidden = (const float*)d_in[1];
    const float* enc = (const float*)d_in[2];
    const float* emb = (const float*)d_in[3];
    const float* W_w = (const float*)d_in[4];
    const float* W_b = (const float*)d_in[5];
    const float* U_w = (const float*)d_in[6];
    const float* U_b = (const float*)d_in[7];
    const float* v_w = (const float*)d_in[8];
    // d_in[9] = v_b : constant over S, cancels in softmax
    const float* ih_w = (const float*)d_in[10];
    const float* ih_b = (const float*)d_in[11];
    const float* hh_w = (const float*)d_in[12];
    const float* hh_b = (const float*)d_in[13];
    const float* cand_w = (const float*)d_in[14];
    const float* cand_b = (const float*)d_in[15];
    const float* hhc_w = (const float*)d_in[16];
    const float* hhc_b = (const float*)d_in[17];
    const float* comb_w = (const float*)d_in[18];
    const float* comb_b = (const float*)d_in[19];
    const float* ln_g = (const float*)d_in[20];
    const float* ln_b = (const float*)d_in[21];
    const float* out1_w = (const float*)d_in[22];
    const float* out1_b = (const float*)d_in[23];
    const float* out2_w = (const float*)d_in[24];
    const float* out2_b = (const float*)d_in[25];

    float* out_logits = (float*)d_out;
    float* out_h = out_logits + (size_t)BATCH * VDIM;
    float* out_attn = out_h + (size_t)BATCH * HDIM;

    float *Wh, *score, *ctx, *gbuf, *gates, *t1, *t2, *o1;
    __half *encH, *o1h;
    uint32_t *UwP, *out2P;
    cudaGetSymbolAddress((void**)&Wh, g_Wh);
    cudaGetSymbolAddress((void**)&score, g_score);
    cudaGetSymbolAddress((void**)&ctx, g_ctx);
    cudaGetSymbolAddress((void**)&gbuf, g_g);
    cudaGetSymbolAddress((void**)&gates, g_gates);
    cudaGetSymbolAddress((void**)&t1, g_t1);
    cudaGetSymbolAddress((void**)&t2, g_t2);
    cudaGetSymbolAddress((void**)&o1, g_o1);
    cudaGetSymbolAddress((void**)&encH, g_encH);
    cudaGetSymbolAddress((void**)&o1h, g_o1h);
    cudaGetSymbolAddress((void**)&UwP, g_UwP);
    cudaGetSymbolAddress((void**)&out2P, g_out2P);

    cudaFuncSetAttribute(tgemm256h<ScoreH>,
                         cudaFuncAttributeMaxDynamicSharedMemorySize, SMEMH);
    cudaFuncSetAttribute(tgemm256h<Out2H>,
                         cudaFuncAttributeMaxDynamicSharedMemorySize, SMEMH);

    // 0. conversions
    f2h_kernel<<<(SDIM * BATCH * HDIM) / 1024, 256>>>(enc, encH, SDIM * BATCH * HDIM);
    packb_kernel<<<dim3(HDIM / 256, HDIM / 2), 256>>>(U_w, UwP, HDIM, HDIM);
    packb_kernel<<<dim3(VPAD / 256, HDIM / 2), 256>>>(out2_w, out2P, VDIM, VPAD);

    // 1. Wh = hidden @ W_w + W_b (tf32, 64x64 tiles)
    {
        Plain64 p{hidden, W_w, W_b, Wh, HDIM, HDIM, 0};
        tgemm64<Plain64><<<dim3(HDIM / 64, BATCH / 64), 128>>>(p);
    }
    // 2. zero score
    zero_kernel<<<(SDIM * BATCH + 255) / 256, 256>>>(score, SDIM * BATCH);
    // 3. fused score GEMM (fp16 tensor core)
    {
        ScoreH p{encH, UwP, Wh, U_b, v_w, score, HDIM};
        tgemm256h<ScoreH><<<dim3(HDIM / 256, (SDIM * BATCH) / 128), 256, SMEMH>>>(p);
    }
    // 4. softmax -> attn output
    softmax_kernel<<<BATCH, SDIM>>>(score, out_attn);
    // 5. context
    context_kernel<<<BATCH, 256>>>(enc, out_attn, ctx);
    // 6. g = relu([emb[ids], ctx] @ comb_w + comb_b)
    {
        Comb64 p{emb, ids, ctx, comb_w, comb_b, gbuf, EDIM + HDIM};
        tgemm64<Comb64><<<dim3(EDIM / 64, BATCH / 64), 128>>>(p);
    }
    // 7. fused gates | t1 | t2
    {
        Fused3_64 p{gbuf, hidden, ih_w, hh_w, cand_w, hhc_w,
                    ih_b, hh_b, cand_b, hhc_b, gates, t1, t2, EDIM + HDIM};
        tgemm64<Fused3_64><<<dim3(4096 / 64, BATCH / 64), 128>>>(p);
    }
    // 8. GRU combine + LayerNorm
    fuse_hln_kernel<<<BATCH, 256>>>(gates, t1, t2, hidden, ln_g, ln_b, out_h);
    // 9. o1 = relu(h @ out1_w + out1_b), then fp16 copy
    {
        Plain64 p{out_h, out1_w, out1_b, o1, HDIM, HDIM, 1};
        tgemm64<Plain64><<<dim3(HDIM / 64, BATCH / 64), 128>>>(p);
    }
    f2h_kernel<<<(BATCH * HDIM) / 1024, 256>>>(o1, o1h, BATCH * HDIM);
    // 10. logits = o1h @ out2P + out2_b (fp16 tensor core)
    {
        Out2H p{o1h, out2P, out2_b, out_logits, HDIM, VDIM};
        tgemm256h<Out2H><<<dim3((VDIM + 255) / 256, BATCH / 128), 256, SMEMH>>>(p);
    }
    // 11. log_softmax
    logsoftmax_kernel<<<BATCH, 512>>>(out_logits);
}